// round 5
// baseline (speedup 1.0000x reference)
#include <cuda_runtime.h>
#include <math.h>

// ---------------------------------------------------------------------------
// TriangleAttention  (B=1, N=256, IN_DIM=128, H=4, D=32)
// R5: SIMT, smem-bandwidth-optimized.
//   GEMMs: 128x128 tiles, 8x8 microtile, f32x2 FMA (fma-pipe-bound).
//   Attention: 8-row passes, swizzled Ks for LDS.128, pair-packed Aw for AV.
// ---------------------------------------------------------------------------

#define NPOS 65536
#define NSEQ 256
#define INDIM 128
#define NH 4
#define HD 32

typedef unsigned long long u64;

__device__ __forceinline__ u64 pk2(float lo, float hi) {
    u64 r; asm("mov.b64 %0, {%1,%2};" : "=l"(r) : "f"(lo), "f"(hi)); return r;
}
__device__ __forceinline__ u64 dup2(float v) { return pk2(v, v); }
__device__ __forceinline__ void upk2(u64 p, float& lo, float& hi) {
    asm("mov.b64 {%0,%1}, %2;" : "=f"(lo), "=f"(hi) : "l"(p));
}
__device__ __forceinline__ u64 ffma2(u64 a, u64 b, u64 c) {
    u64 d; asm("fma.rn.f32x2 %0, %1, %2, %3;" : "=l"(d) : "l"(a), "l"(b), "l"(c));
    return d;
}

#define COMP(v, e) ((e) == 0 ? (v).x : (e) == 1 ? (v).y : (e) == 2 ? (v).z : (v).w)

// Scratch (static device memory)
__device__ __align__(16) float g_zn[NPOS * INDIM];
__device__ __align__(16) float g_q[NPOS * INDIM];      // [r][h][i][d]
__device__ __align__(16) float g_k[NPOS * INDIM];      // [r][h][j][d]
__device__ __align__(16) float g_v[NPOS * INDIM];      // [r][h][j][d]
__device__ __align__(16) float g_pb[NH * NPOS];        // [h][i][j]
__device__ __align__(16) float g_gate[NPOS * INDIM];
__device__ __align__(16) float g_ao[NPOS * INDIM];

__device__ __forceinline__ float warp_sum(float v) {
    #pragma unroll
    for (int o = 16; o; o >>= 1) v += __shfl_xor_sync(0xffffffffu, v, o);
    return v;
}
__device__ __forceinline__ float warp_max(float v) {
    #pragma unroll
    for (int o = 16; o; o >>= 1) v = fmaxf(v, __shfl_xor_sync(0xffffffffu, v, o));
    return v;
}

// ---------------------------------------------------------------------------
// LayerNorm
// ---------------------------------------------------------------------------
__global__ void __launch_bounds__(256) ln_kernel(
    const float* __restrict__ z, const float* __restrict__ g,
    const float* __restrict__ b)
{
    int w = threadIdx.x >> 5, lane = threadIdx.x & 31;
    int row = blockIdx.x * 8 + w;
    float4 zv = *(const float4*)&z[row * INDIM + (lane << 2)];
    float s  = zv.x + zv.y + zv.z + zv.w;
    float s2 = zv.x * zv.x + zv.y * zv.y + zv.z * zv.z + zv.w * zv.w;
    s = warp_sum(s);
    s2 = warp_sum(s2);
    float mu = s * (1.0f / 128.0f);
    float var = s2 * (1.0f / 128.0f) - mu * mu;
    float rs = rsqrtf(var + 1e-5f);
    float4 gv = *(const float4*)&g[lane << 2];
    float4 bv = *(const float4*)&b[lane << 2];
    float4 o;
    o.x = (zv.x - mu) * rs * gv.x + bv.x;
    o.y = (zv.y - mu) * rs * gv.y + bv.y;
    o.z = (zv.z - mu) * rs * gv.z + bv.z;
    o.w = (zv.w - mu) * rs * gv.w + bv.w;
    *(float4*)&g_zn[row * INDIM + (lane << 2)] = o;
}

// ---------------------------------------------------------------------------
// GEMM: C[M=65536, NTOT] = A[M,128] @ B[128,NTOT]
// 128x128 block tile, 256 threads, 8x8 microtile, k-chunks of 32.
// MODE 0: A=zn, scatter qkv (NTOT=384)
// MODE 1: A=zn, sigmoid(x+bias) -> g_gate (NTOT=128)
// MODE 2: A=gate*ao, x+bias -> dout (NTOT=128)
// ---------------------------------------------------------------------------
template <int MODE>
__global__ void __launch_bounds__(256, 2) gemm_kernel(
    int NTOT, const float* __restrict__ B,
    const float* __restrict__ bias, float* __restrict__ dout)
{
    __shared__ float As[32][132];   // [k][m]
    __shared__ float Bs[32][132];   // [k][n]

    int tid = threadIdx.x;
    int tx = tid & 15, ty = tid >> 4;
    int m0 = blockIdx.y << 7, n0 = blockIdx.x << 7;

    u64 acc2[8][4];
    #pragma unroll
    for (int i = 0; i < 8; i++)
        #pragma unroll
        for (int t = 0; t < 4; t++) acc2[i][t] = 0ull;

    for (int kc = 0; kc < 128; kc += 32) {
        // A: 128 rows x 32 k = 1024 float4 (coalesced: 8 lanes span a k-row chunk)
        #pragma unroll
        for (int t = 0; t < 4; t++) {
            int f = tid + (t << 8);        // 0..1023
            int m = f >> 3;                // 0..127
            int k4 = (f & 7) << 2;         // 0,4,...,28
            int gi = (m0 + m) * INDIM + kc + k4;
            float4 a;
            if (MODE == 2) {
                float4 x = *(const float4*)&g_ao[gi];
                float4 gt = *(const float4*)&g_gate[gi];
                a.x = x.x * gt.x; a.y = x.y * gt.y;
                a.z = x.z * gt.z; a.w = x.w * gt.w;
            } else {
                a = *(const float4*)&g_zn[gi];
            }
            As[k4 + 0][m] = a.x; As[k4 + 1][m] = a.y;
            As[k4 + 2][m] = a.z; As[k4 + 3][m] = a.w;
        }
        // B: 32 k x 128 n = 1024 float4 (coalesced over n)
        #pragma unroll
        for (int t = 0; t < 4; t++) {
            int f = tid + (t << 8);
            int n4 = (f & 31) << 2;
            int k = f >> 5;                // 0..31
            float4 b4 = *(const float4*)&B[(kc + k) * NTOT + n0 + n4];
            *(float4*)&Bs[k][n4] = b4;
        }
        __syncthreads();

        #pragma unroll 8
        for (int k = 0; k < 32; k++) {
            float4 a0 = *(const float4*)&As[k][ty << 3];
            float4 a1 = *(const float4*)&As[k][(ty << 3) + 4];
            float4 b0 = *(const float4*)&Bs[k][tx << 3];
            float4 b1 = *(const float4*)&Bs[k][(tx << 3) + 4];
            u64 bp[4] = {pk2(b0.x, b0.y), pk2(b0.z, b0.w),
                         pk2(b1.x, b1.y), pk2(b1.z, b1.w)};
            float am[8] = {a0.x, a0.y, a0.z, a0.w, a1.x, a1.y, a1.z, a1.w};
            #pragma unroll
            for (int i = 0; i < 8; i++) {
                u64 a2 = dup2(am[i]);
                #pragma unroll
                for (int t = 0; t < 4; t++)
                    acc2[i][t] = ffma2(a2, bp[t], acc2[i][t]);
            }
        }
        __syncthreads();
    }

    // epilogue: rows m0+ty*8+i, col groups n0+tx*8 (+4)
    #pragma unroll
    for (int i = 0; i < 8; i++) {
        int p = m0 + (ty << 3) + i;
        #pragma unroll
        for (int g = 0; g < 2; g++) {
            int nb = n0 + (tx << 3) + (g << 2);
            float4 res;
            upk2(acc2[i][g * 2 + 0], res.x, res.y);
            upk2(acc2[i][g * 2 + 1], res.z, res.w);
            if (MODE == 0) {
                int seg = nb >> 7, nl = nb & 127, h = nl >> 5, dd = nl & 31;
                int r = p >> 8, ii = p & 255;
                float* dst = (seg == 0) ? g_q : ((seg == 1) ? g_k : g_v);
                *(float4*)&dst[((r * NH + h) * NSEQ + ii) * HD + dd] = res;
            } else if (MODE == 1) {
                float4 bb = *(const float4*)&bias[nb];
                res.x = 1.0f / (1.0f + __expf(-(res.x + bb.x)));
                res.y = 1.0f / (1.0f + __expf(-(res.y + bb.y)));
                res.z = 1.0f / (1.0f + __expf(-(res.z + bb.z)));
                res.w = 1.0f / (1.0f + __expf(-(res.w + bb.w)));
                *(float4*)&g_gate[p * INDIM + nb] = res;
            } else {
                float4 bb = *(const float4*)&bias[nb];
                res.x += bb.x; res.y += bb.y; res.z += bb.z; res.w += bb.w;
                *(float4*)&dout[p * INDIM + nb] = res;
            }
        }
    }
}

// ---------------------------------------------------------------------------
// Pair bias
// ---------------------------------------------------------------------------
__global__ void __launch_bounds__(128) pb_kernel(const float* __restrict__ w_pair)
{
    int w = threadIdx.x >> 5, lane = threadIdx.x & 31;
    int p = blockIdx.x * 4 + w;
    float4 zv = *(const float4*)&g_zn[p * INDIM + (lane << 2)];
    const float4* W = (const float4*)w_pair;
    int k0 = lane << 2;
    float4 w0 = W[k0], w1 = W[k0 + 1], w2 = W[k0 + 2], w3 = W[k0 + 3];
    float4 a;
    a.x = zv.x * w0.x + zv.y * w1.x + zv.z * w2.x + zv.w * w3.x;
    a.y = zv.x * w0.y + zv.y * w1.y + zv.z * w2.y + zv.w * w3.y;
    a.z = zv.x * w0.z + zv.y * w1.z + zv.z * w2.z + zv.w * w3.z;
    a.w = zv.x * w0.w + zv.y * w1.w + zv.z * w2.w + zv.w * w3.w;
    a.x = warp_sum(a.x); a.y = warp_sum(a.y);
    a.z = warp_sum(a.z); a.w = warp_sum(a.w);
    if (lane == 0) {
        g_pb[0 * NPOS + p] = a.x;
        g_pb[1 * NPOS + p] = a.y;
        g_pb[2 * NPOS + p] = a.z;
        g_pb[3 * NPOS + p] = a.w;
    }
}

// ---------------------------------------------------------------------------
// Attention: one block per (h, r). 8 warps; each warp owns 32 i-rows,
// processed 8 at a time (4 passes). Ks [256][32] XOR-swizzled for LDS.128;
// Vs [256][33]; Aw [warp][256][8] pre-packed row-pairs for AV ffma2.
// smem floats: Ks 8192 | Vs 8448 | Aw 16384 | msk 256  = 133120 bytes
// ---------------------------------------------------------------------------
__global__ void __launch_bounds__(256, 1) attn_kernel(const int* __restrict__ smask)
{
    extern __shared__ float sm[];
    float* Ks = sm;                  // 8192
    float* Vs = sm + 8192;           // 8448
    float* Aw = sm + 16640;          // 16384
    int*   msk = (int*)(sm + 33024);

    int h = blockIdx.x, r = blockIdx.y;
    int tid = threadIdx.x;
    int base = (r * NH + h) << 13;   // *(256*32)

    // stage K (swizzled chunks) and V (stride-33)
    #pragma unroll
    for (int t = 0; t < 8; t++) {
        int idx = (tid << 2) + (t << 10);
        int j = idx >> 5, d = idx & 31;       // d multiple of 4
        float4 k4 = *(const float4*)&g_k[base + idx];
        *(float4*)&Ks[(j << 5) + (((d >> 2) ^ (j & 7)) << 2)] = k4;
        float4 v4 = *(const float4*)&g_v[base + idx];
        Vs[j * 33 + d] = v4.x; Vs[j * 33 + d + 1] = v4.y;
        Vs[j * 33 + d + 2] = v4.z; Vs[j * 33 + d + 3] = v4.w;
    }
    msk[tid] = (smask[tid] == 0) ? 1 : 0;
    __syncthreads();

    int w = tid >> 5, lane = tid & 31;
    const float invs = 0.17677669529663687f;  // 1/sqrt(32)
    float* awb = &Aw[w << 11];                 // warp's [256][8] region
    int swl = (lane & 7);

    for (int gp = 0; gp < 4; gp++) {
        int i0 = (w << 5) + (gp << 3);
        float qreg[8];
        #pragma unroll
        for (int ii = 0; ii < 8; ii++)
            qreg[ii] = g_q[base + ((i0 + ii) << 5) + lane];

        u64 acc2[8][4];
        #pragma unroll
        for (int ii = 0; ii < 8; ii++)
            #pragma unroll
            for (int t = 0; t < 4; t++) acc2[ii][t] = 0ull;

        // ---- S = Q K^T : 8 rows x 256 j per warp
        #pragma unroll 2
        for (int d4 = 0; d4 < 8; d4++) {
            float4 kv4[8];
            #pragma unroll
            for (int jj = 0; jj < 8; jj++)
                kv4[jj] = *(const float4*)&Ks[(((jj << 5) + lane) << 5)
                                              + ((d4 ^ swl) << 2)];
            #pragma unroll
            for (int e = 0; e < 4; e++) {
                int d = (d4 << 2) + e;
                u64 kp[4];
                #pragma unroll
                for (int t = 0; t < 4; t++)
                    kp[t] = pk2(COMP(kv4[2 * t], e), COMP(kv4[2 * t + 1], e));
                #pragma unroll
                for (int ii = 0; ii < 8; ii++) {
                    u64 q2 = dup2(__shfl_sync(0xffffffffu, qreg[ii], d));
                    #pragma unroll
                    for (int t = 0; t < 4; t++)
                        acc2[ii][t] = ffma2(q2, kp[t], acc2[ii][t]);
                }
            }
        }

        // ---- softmax (faithful: masked -> -1e-9, not -inf)
        float prob[8][8];
        #pragma unroll
        for (int ii = 0; ii < 8; ii++) {
            int i = i0 + ii;
            int mi = msk[i];
            const float* pbrow = &g_pb[(h << 16) + (i << 8)];
            float l[8];
            #pragma unroll
            for (int t = 0; t < 4; t++)
                upk2(acc2[ii][t], l[2 * t], l[2 * t + 1]);
            float mx = -1e30f;
            #pragma unroll
            for (int jj = 0; jj < 8; jj++) {
                int j = (jj << 5) + lane;
                float lv = fmaf(l[jj], invs, pbrow[j]);
                if (mi ^ msk[j]) lv = -1e-9f;
                l[jj] = lv;
                mx = fmaxf(mx, lv);
            }
            mx = warp_max(mx);
            float s = 0.0f;
            #pragma unroll
            for (int jj = 0; jj < 8; jj++) {
                float e = __expf(l[jj] - mx);
                l[jj] = e;
                s += e;
            }
            s = warp_sum(s);
            float inv = 1.0f / s;
            #pragma unroll
            for (int jj = 0; jj < 8; jj++) prob[ii][jj] = l[jj] * inv;
        }
        // store probs pair-packed: Aw[j][0..7] = prob[0..7] at column j
        #pragma unroll
        for (int jj = 0; jj < 8; jj++) {
            int j = (jj << 5) + lane;
            float4 lo = make_float4(prob[0][jj], prob[1][jj],
                                    prob[2][jj], prob[3][jj]);
            float4 hi = make_float4(prob[4][jj], prob[5][jj],
                                    prob[6][jj], prob[7][jj]);
            *(float4*)&awb[(j << 3)] = lo;
            *(float4*)&awb[(j << 3) + 4] = hi;
        }
        __syncwarp();

        // ---- O = A V  (lane = d); ulonglong2 loads give ffma2 operand pairs
        u64 o2[4] = {0ull, 0ull, 0ull, 0ull};
        #pragma unroll 4
        for (int j = 0; j < 256; j++) {
            u64 v2 = dup2(Vs[j * 33 + lane]);
            ulonglong2 p01 = *(const ulonglong2*)&awb[(j << 3)];
            ulonglong2 p23 = *(const ulonglong2*)&awb[(j << 3) + 4];
            o2[0] = ffma2(p01.x, v2, o2[0]);
            o2[1] = ffma2(p01.y, v2, o2[1]);
            o2[2] = ffma2(p23.x, v2, o2[2]);
            o2[3] = ffma2(p23.y, v2, o2[3]);
        }
        int ob = ((r << 8) + i0) * INDIM + (h << 5) + lane;
        #pragma unroll
        for (int t = 0; t < 4; t++) {
            float e0, e1;
            upk2(o2[t], e0, e1);
            g_ao[ob + (2 * t) * INDIM] = e0;
            g_ao[ob + (2 * t + 1) * INDIM] = e1;
        }
        __syncwarp();
    }
}

// ---------------------------------------------------------------------------
extern "C" void kernel_launch(void* const* d_in, const int* in_sizes, int n_in,
                              void* d_out, int out_size)
{
    const float* z      = (const float*)d_in[0];
    const int*   smask  = (const int*)  d_in[1];
    const float* ln_g   = (const float*)d_in[2];
    const float* ln_b   = (const float*)d_in[3];
    const float* w_qkv  = (const float*)d_in[4];
    const float* w_pair = (const float*)d_in[5];
    const float* w_gate = (const float*)d_in[6];
    const float* b_gate = (const float*)d_in[7];
    const float* w_out  = (const float*)d_in[8];
    const float* b_out  = (const float*)d_in[9];
    float* out = (float*)d_out;

    const int ATT_SMEM = 133120;
    cudaFuncSetAttribute(attn_kernel,
                         cudaFuncAttributeMaxDynamicSharedMemorySize, ATT_SMEM);

    ln_kernel<<<8192, 256>>>(z, ln_g, ln_b);
    gemm_kernel<0><<<dim3(3, 512), 256>>>(384, w_qkv, nullptr, nullptr);
    pb_kernel<<<16384, 128>>>(w_pair);
    gemm_kernel<1><<<dim3(1, 512), 256>>>(128, w_gate, b_gate, nullptr);
    attn_kernel<<<dim3(4, 256), 256, ATT_SMEM>>>(smask);
    gemm_kernel<2><<<dim3(1, 512), 256>>>(128, w_out, b_out, out);
}

// round 8
// speedup vs baseline: 1.3941x; 1.3941x over previous
#include <cuda_runtime.h>
#include <cuda_bf16.h>
#include <math.h>
#include <stdint.h>

// ---------------------------------------------------------------------------
// TriangleAttention  (B=1, N=256, IN_DIM=128, H=4, D=32)
// R8: R7 with the A-tile staging loop fixed for 256 threads
//     (was a 128-thread loop -> OOB smem writes corrupted A-lo rows 0-3).
// Projections: warp-level mma.sync bf16, split 3-pass, fp32 accum.
// ---------------------------------------------------------------------------

#define NPOS 65536
#define NSEQ 256
#define INDIM 128
#define NH 4
#define HD 32

typedef unsigned long long u64;

// ---------------- scratch ----------------
__device__ __align__(16) float g_zn[NPOS * INDIM];
__device__ __align__(16) float g_q[NPOS * INDIM];      // [r][h][i][d]
__device__ __align__(16) float g_k[NPOS * INDIM];      // [r][h][j][d]
__device__ __align__(16) float g_v[NPOS * INDIM];      // [r][h][j][d]
__device__ __align__(16) float g_pb[NH * NPOS];        // [h][i][j]
__device__ __align__(16) float g_gate[NPOS * INDIM];
__device__ __align__(16) float g_ao[NPOS * INDIM];
// weights transposed to [n][k] and split fp32 -> bf16 hi/lo
__device__ __align__(16) __nv_bfloat16 g_w1h[512 * 128];
__device__ __align__(16) __nv_bfloat16 g_w1l[512 * 128];
__device__ __align__(16) __nv_bfloat16 g_w2h[128 * 128];
__device__ __align__(16) __nv_bfloat16 g_w2l[128 * 128];

// ---------------- helpers ----------------
__device__ __forceinline__ float warp_sum(float v) {
    #pragma unroll
    for (int o = 16; o; o >>= 1) v += __shfl_xor_sync(0xffffffffu, v, o);
    return v;
}
__device__ __forceinline__ float warp_max(float v) {
    #pragma unroll
    for (int o = 16; o; o >>= 1) v = fmaxf(v, __shfl_xor_sync(0xffffffffu, v, o));
    return v;
}
__device__ __forceinline__ u64 pk2(float lo, float hi) {
    u64 r; asm("mov.b64 %0, {%1,%2};" : "=l"(r) : "f"(lo), "f"(hi)); return r;
}
__device__ __forceinline__ u64 dup2(float v) { return pk2(v, v); }
__device__ __forceinline__ void upk2(u64 p, float& lo, float& hi) {
    asm("mov.b64 {%0,%1}, %2;" : "=f"(lo), "=f"(hi) : "l"(p));
}
__device__ __forceinline__ u64 ffma2(u64 a, u64 b, u64 c) {
    u64 d; asm("fma.rn.f32x2 %0, %1, %2, %3;" : "=l"(d) : "l"(a), "l"(b), "l"(c));
    return d;
}
__device__ __forceinline__ uint32_t smem_u32(const void* p) {
    uint32_t a;
    asm("{ .reg .u64 t; cvta.to.shared.u64 t, %1; cvt.u32.u64 %0, t; }"
        : "=r"(a) : "l"(p));
    return a;
}

// ---- warp-level MMA primitives (sm_80-era; no tcgen05) ----
__device__ __forceinline__ void ldsm_x4(uint32_t* r, uint32_t addr) {
    asm volatile("ldmatrix.sync.aligned.m8n8.x4.shared.b16 {%0,%1,%2,%3}, [%4];"
                 : "=r"(r[0]), "=r"(r[1]), "=r"(r[2]), "=r"(r[3]) : "r"(addr));
}
__device__ __forceinline__ void ldsm_x2(uint32_t* r, uint32_t addr) {
    asm volatile("ldmatrix.sync.aligned.m8n8.x2.shared.b16 {%0,%1}, [%2];"
                 : "=r"(r[0]), "=r"(r[1]) : "r"(addr));
}
__device__ __forceinline__ void mma_bf16(float* d, const uint32_t* a,
                                         const uint32_t* b) {
    asm volatile(
        "mma.sync.aligned.m16n8k16.row.col.f32.bf16.bf16.f32 "
        "{%0,%1,%2,%3}, {%4,%5,%6,%7}, {%8,%9}, {%0,%1,%2,%3};"
        : "+f"(d[0]), "+f"(d[1]), "+f"(d[2]), "+f"(d[3])
        : "r"(a[0]), "r"(a[1]), "r"(a[2]), "r"(a[3]), "r"(b[0]), "r"(b[1]));
}

// ---------------------------------------------------------------------------
// LayerNorm
// ---------------------------------------------------------------------------
__global__ void __launch_bounds__(256) ln_kernel(
    const float* __restrict__ z, const float* __restrict__ g,
    const float* __restrict__ b)
{
    int w = threadIdx.x >> 5, lane = threadIdx.x & 31;
    int row = blockIdx.x * 8 + w;
    float4 zv = *(const float4*)&z[row * INDIM + (lane << 2)];
    float s  = zv.x + zv.y + zv.z + zv.w;
    float s2 = zv.x * zv.x + zv.y * zv.y + zv.z * zv.z + zv.w * zv.w;
    s = warp_sum(s);
    s2 = warp_sum(s2);
    float mu = s * (1.0f / 128.0f);
    float var = s2 * (1.0f / 128.0f) - mu * mu;
    float rs = rsqrtf(var + 1e-5f);
    float4 gv = *(const float4*)&g[lane << 2];
    float4 bv = *(const float4*)&b[lane << 2];
    float4 o;
    o.x = (zv.x - mu) * rs * gv.x + bv.x;
    o.y = (zv.y - mu) * rs * gv.y + bv.y;
    o.z = (zv.z - mu) * rs * gv.z + bv.z;
    o.w = (zv.w - mu) * rs * gv.w + bv.w;
    *(float4*)&g_zn[row * INDIM + (lane << 2)] = o;
}

// ---------------------------------------------------------------------------
// Weight prep: transpose to [n][k], split fp32 -> bf16 hi/lo
// ---------------------------------------------------------------------------
__global__ void __launch_bounds__(256) prep_w(
    const float* __restrict__ wqkv, const float* __restrict__ wgate,
    const float* __restrict__ wout)
{
    int idx = blockIdx.x * 256 + threadIdx.x;   // 0..81919
    int n = idx >> 7, k = idx & 127;
    float x;
    if (n < 384)      x = wqkv[k * 384 + n];
    else if (n < 512) x = wgate[k * 128 + (n - 384)];
    else              x = wout[k * 128 + (n - 512)];
    __nv_bfloat16 h = __float2bfloat16(x);
    __nv_bfloat16 l = __float2bfloat16(x - __bfloat162float(h));
    if (n < 512) { g_w1h[n * 128 + k] = h; g_w1l[n * 128 + k] = l; }
    else { g_w2h[(n - 512) * 128 + k] = h; g_w2l[(n - 512) * 128 + k] = l; }
}

// ---------------------------------------------------------------------------
// Projection GEMM via mma.sync, split-bf16 3-pass (D += AhBh + AhBl + AlBh).
// CTA: M=128 x N=64 tile, K=128.  8 warps = 2(M) x 4(N); warp tile 64x16.
// smem pitch 272B (136 bf16): ldmatrix conflict-free (272 mod 128 = 16).
// WHICH=0: A=zn, NT=8 (cols 0..383 qkv scatter, 384..511 gate+sigmoid)
// WHICH=1: A=gate*ao, NT=2 (out proj + bias -> dout)
// ---------------------------------------------------------------------------
#define PITCHU 68            // uints per row (136 bf16 = 272 B)
#define OFF_AH 0
#define OFF_AL 34816
#define OFF_BH 69632
#define OFF_BL 87040
#define PROJ_SMEM 104448

template <int WHICH>
__global__ void __launch_bounds__(256) proj_mma(
    const float* __restrict__ bgate, const float* __restrict__ bout,
    float* __restrict__ dout)
{
    extern __shared__ char smem[];
    uint32_t sb = smem_u32(smem);
    uint32_t* smU = (uint32_t*)smem;

    int tid = threadIdx.x, wid = tid >> 5, lane = tid & 31;
    int warp_m = wid >> 2, warp_n = wid & 3;
    int g = lane >> 2, tg = lane & 3;
    int m0 = blockIdx.x << 7;

    // ---- A tile: 128x128 fp32 -> split bf16 into [row][PITCHU] (both splits)
    // 256 threads x 16 iters = 4096 float4, disjoint exact cover. (R7 bug fix)
    #pragma unroll 4
    for (int t = 0; t < 16; t++) {
        int e4 = tid + (t << 8);            // float4 idx 0..4095
        int m = e4 >> 5;
        int k4 = (e4 & 31) << 2;
        int gi = (m0 + m) * INDIM + k4;
        float4 a;
        if (WHICH == 1) {
            float4 x = *(const float4*)&g_ao[gi];
            float4 gt = *(const float4*)&g_gate[gi];
            a.x = x.x * gt.x; a.y = x.y * gt.y;
            a.z = x.z * gt.z; a.w = x.w * gt.w;
        } else {
            a = *(const float4*)&g_zn[gi];
        }
        __nv_bfloat16 h0 = __float2bfloat16(a.x), h1 = __float2bfloat16(a.y);
        __nv_bfloat16 h2 = __float2bfloat16(a.z), h3 = __float2bfloat16(a.w);
        __nv_bfloat16 l0 = __float2bfloat16(a.x - __bfloat162float(h0));
        __nv_bfloat16 l1 = __float2bfloat16(a.y - __bfloat162float(h1));
        __nv_bfloat16 l2 = __float2bfloat16(a.z - __bfloat162float(h2));
        __nv_bfloat16 l3 = __float2bfloat16(a.w - __bfloat162float(h3));
        uint2 hh, ll;
        hh.x = ((uint32_t)__bfloat16_as_ushort(h1) << 16) | __bfloat16_as_ushort(h0);
        hh.y = ((uint32_t)__bfloat16_as_ushort(h3) << 16) | __bfloat16_as_ushort(h2);
        ll.x = ((uint32_t)__bfloat16_as_ushort(l1) << 16) | __bfloat16_as_ushort(l0);
        ll.y = ((uint32_t)__bfloat16_as_ushort(l3) << 16) | __bfloat16_as_ushort(l2);
        int du = m * PITCHU + (k4 >> 1);
        *(uint2*)&smU[(OFF_AH >> 2) + du] = hh;
        *(uint2*)&smU[(OFF_AL >> 2) + du] = ll;
    }
    __syncthreads();

    const int NT = (WHICH == 0) ? 8 : 2;
    for (int nt = 0; nt < NT; nt++) {
        int nbase = nt << 6;
        const __nv_bfloat16* WH = (WHICH == 0) ? g_w1h : g_w2h;
        const __nv_bfloat16* WL = (WHICH == 0) ? g_w1l : g_w2l;
        // B tile: 64 rows x 128 k (both splits) into [row][PITCHU]
        #pragma unroll
        for (int t = 0; t < 8; t++) {
            int f = tid + (t << 8);          // uint2 idx 0..2047, disjoint
            int row = f >> 5;
            int cu2 = (f & 31);              // uint2 within row
            uint2 hh = *(const uint2*)&WH[(nbase + row) * 128 + (cu2 << 2)];
            uint2 ll = *(const uint2*)&WL[(nbase + row) * 128 + (cu2 << 2)];
            int du = row * PITCHU + (cu2 << 1);
            *(uint2*)&smU[(OFF_BH >> 2) + du] = hh;
            *(uint2*)&smU[(OFF_BL >> 2) + du] = ll;
        }
        __syncthreads();

        float d[4][2][4];
        #pragma unroll
        for (int mt = 0; mt < 4; mt++)
            #pragma unroll
            for (int ntl = 0; ntl < 2; ntl++)
                #pragma unroll
                for (int e = 0; e < 4; e++) d[mt][ntl][e] = 0.0f;

        // per-thread ldmatrix row addresses
        int arow = (warp_m << 6) + (lane & 15);
        uint32_t a_off = (uint32_t)(arow * 272 + ((lane >> 4) << 4));
        int brow = (warp_n << 4) + (lane & 7);
        uint32_t b_off = (uint32_t)(brow * 272 + (((lane >> 3) & 1) << 4));
        uint32_t b2_off = b_off + 8 * 272;   // second n8 tile

        #pragma unroll 2
        for (int ks = 0; ks < 8; ks++) {
            uint32_t koff = (uint32_t)(ks << 5);
            uint32_t a[4][4], bh[2][2], bl[2][2];
            #pragma unroll
            for (int mt = 0; mt < 4; mt++)
                ldsm_x4(a[mt], sb + OFF_AH + a_off + (uint32_t)(mt * 16 * 272) + koff);
            ldsm_x2(bh[0], sb + OFF_BH + b_off + koff);
            ldsm_x2(bh[1], sb + OFF_BH + b2_off + koff);
            ldsm_x2(bl[0], sb + OFF_BL + b_off + koff);
            ldsm_x2(bl[1], sb + OFF_BL + b2_off + koff);
            #pragma unroll
            for (int mt = 0; mt < 4; mt++) {
                mma_bf16(d[mt][0], a[mt], bh[0]);
                mma_bf16(d[mt][1], a[mt], bh[1]);
            }
            #pragma unroll
            for (int mt = 0; mt < 4; mt++) {
                mma_bf16(d[mt][0], a[mt], bl[0]);
                mma_bf16(d[mt][1], a[mt], bl[1]);
            }
            #pragma unroll
            for (int mt = 0; mt < 4; mt++)
                ldsm_x4(a[mt], sb + OFF_AL + a_off + (uint32_t)(mt * 16 * 272) + koff);
            #pragma unroll
            for (int mt = 0; mt < 4; mt++) {
                mma_bf16(d[mt][0], a[mt], bh[0]);
                mma_bf16(d[mt][1], a[mt], bh[1]);
            }
        }
        __syncthreads();   // compute done; safe to overwrite B next nt

        // ---- epilogue from register frags
        #pragma unroll
        for (int mt = 0; mt < 4; mt++) {
            int p0 = m0 + (warp_m << 6) + (mt << 4) + g;
            #pragma unroll
            for (int ntl = 0; ntl < 2; ntl++) {
                int n = nbase + (warp_n << 4) + (ntl << 3) + (tg << 1);
                #pragma unroll
                for (int half = 0; half < 2; half++) {
                    int p = p0 + half * 8;
                    float v0 = d[mt][ntl][half * 2 + 0];
                    float v1 = d[mt][ntl][half * 2 + 1];
                    if (WHICH == 0) {
                        if (n < 384) {
                            int seg = n >> 7, nl = n & 127, h = nl >> 5, dd = nl & 31;
                            int r = p >> 8, i = p & 255;
                            float* dst = (seg == 0) ? g_q : ((seg == 1) ? g_k : g_v);
                            float2 v = make_float2(v0, v1);
                            *(float2*)&dst[((r * NH + h) * NSEQ + i) * HD + dd] = v;
                        } else {
                            int gc = n - 384;
                            float2 bb = *(const float2*)&bgate[gc];
                            float2 v;
                            v.x = 1.0f / (1.0f + __expf(-(v0 + bb.x)));
                            v.y = 1.0f / (1.0f + __expf(-(v1 + bb.y)));
                            *(float2*)&g_gate[p * INDIM + gc] = v;
                        }
                    } else {
                        float2 bb = *(const float2*)&bout[n];
                        float2 v = make_float2(v0 + bb.x, v1 + bb.y);
                        *(float2*)&dout[p * INDIM + n] = v;
                    }
                }
            }
        }
    }
}

// ---------------------------------------------------------------------------
// Pair bias
// ---------------------------------------------------------------------------
__global__ void __launch_bounds__(128) pb_kernel(const float* __restrict__ w_pair)
{
    int w = threadIdx.x >> 5, lane = threadIdx.x & 31;
    int p = blockIdx.x * 4 + w;
    float4 zv = *(const float4*)&g_zn[p * INDIM + (lane << 2)];
    const float4* W = (const float4*)w_pair;
    int k0 = lane << 2;
    float4 w0 = W[k0], w1 = W[k0 + 1], w2 = W[k0 + 2], w3 = W[k0 + 3];
    float4 a;
    a.x = zv.x * w0.x + zv.y * w1.x + zv.z * w2.x + zv.w * w3.x;
    a.y = zv.x * w0.y + zv.y * w1.y + zv.z * w2.y + zv.w * w3.y;
    a.z = zv.x * w0.z + zv.y * w1.z + zv.z * w2.z + zv.w * w3.z;
    a.w = zv.x * w0.w + zv.y * w1.w + zv.z * w2.w + zv.w * w3.w;
    a.x = warp_sum(a.x); a.y = warp_sum(a.y);
    a.z = warp_sum(a.z); a.w = warp_sum(a.w);
    if (lane == 0) {
        g_pb[0 * NPOS + p] = a.x;
        g_pb[1 * NPOS + p] = a.y;
        g_pb[2 * NPOS + p] = a.z;
        g_pb[3 * NPOS + p] = a.w;
    }
}

// ---------------------------------------------------------------------------
// Attention (exact R2 version — best measured config)
// ---------------------------------------------------------------------------
__global__ void __launch_bounds__(256) attn_kernel(const int* __restrict__ smask)
{
    extern __shared__ float sm[];
    float* Ks = sm;
    float* Vs = sm + 8448;
    float* Aw = sm + 16896;
    int*   msk = (int*)(sm + 25088);

    int h = blockIdx.x, r = blockIdx.y;
    int tid = threadIdx.x;
    int base = (r * NH + h) << 13;

    #pragma unroll
    for (int t = 0; t < 8; t++) {
        int idx = (tid << 2) + (t << 10);
        int j = idx >> 5, d = idx & 31;
        float4 k4 = *(const float4*)&g_k[base + idx];
        Ks[j * 33 + d] = k4.x; Ks[j * 33 + d + 1] = k4.y;
        Ks[j * 33 + d + 2] = k4.z; Ks[j * 33 + d + 3] = k4.w;
        float4 v4 = *(const float4*)&g_v[base + idx];
        Vs[j * 33 + d] = v4.x; Vs[j * 33 + d + 1] = v4.y;
        Vs[j * 33 + d + 2] = v4.z; Vs[j * 33 + d + 3] = v4.w;
    }
    if (tid < 256) msk[tid] = (smask[tid] == 0) ? 1 : 0;
    __syncthreads();

    int w = tid >> 5, lane = tid & 31;
    const float invs = 0.17677669529663687f;
    float* awb = &Aw[w << 10];

    for (int gp = 0; gp < 8; gp++) {
        int i0 = (w << 5) + (gp << 2);
        float qreg[4];
        #pragma unroll
        for (int ii = 0; ii < 4; ii++)
            qreg[ii] = g_q[base + ((i0 + ii) << 5) + lane];

        u64 acc2[4][4];
        #pragma unroll
        for (int ii = 0; ii < 4; ii++)
            #pragma unroll
            for (int t = 0; t < 4; t++) acc2[ii][t] = 0ull;

        #pragma unroll 4
        for (int d = 0; d < 32; d++) {
            float kv[8];
            #pragma unroll
            for (int jj = 0; jj < 8; jj++)
                kv[jj] = Ks[((jj << 5) + lane) * 33 + d];
            u64 kp[4];
            #pragma unroll
            for (int t = 0; t < 4; t++) kp[t] = pk2(kv[2 * t], kv[2 * t + 1]);
            #pragma unroll
            for (int ii = 0; ii < 4; ii++) {
                u64 q2 = dup2(__shfl_sync(0xffffffffu, qreg[ii], d));
                #pragma unroll
                for (int t = 0; t < 4; t++)
                    acc2[ii][t] = ffma2(q2, kp[t], acc2[ii][t]);
            }
        }

        float prob[4][8];
        #pragma unroll
        for (int ii = 0; ii < 4; ii++) {
            int i = i0 + ii;
            int mi = msk[i];
            const float* pbrow = &g_pb[(h << 16) + (i << 8)];
            float l[8];
            #pragma unroll
            for (int t = 0; t < 4; t++)
                upk2(acc2[ii][t], l[2 * t], l[2 * t + 1]);
            float mx = -1e30f;
            #pragma unroll
            for (int jj = 0; jj < 8; jj++) {
                int j = (jj << 5) + lane;
                float lv = fmaf(l[jj], invs, pbrow[j]);
                if (mi ^ msk[j]) lv = -1e-9f;   // faithful: -1e-9, not -inf
                l[jj] = lv;
                mx = fmaxf(mx, lv);
            }
            mx = warp_max(mx);
            float s = 0.0f;
            #pragma unroll
            for (int jj = 0; jj < 8; jj++) {
                float e = __expf(l[jj] - mx);
                l[jj] = e;
                s += e;
            }
            s = warp_sum(s);
            float inv = 1.0f / s;
            #pragma unroll
            for (int jj = 0; jj < 8; jj++) prob[ii][jj] = l[jj] * inv;
        }
        #pragma unroll
        for (int jj = 0; jj < 8; jj++) {
            float4 a4 = make_float4(prob[0][jj], prob[1][jj],
                                    prob[2][jj], prob[3][jj]);
            *(float4*)&awb[(((jj << 5) + lane)) << 2] = a4;
        }
        __syncwarp();

        u64 o2[2] = {0ull, 0ull};
        #pragma unroll 8
        for (int j = 0; j < 256; j++) {
            u64 v2 = dup2(Vs[j * 33 + lane]);
            float4 a4 = *(const float4*)&awb[j << 2];
            o2[0] = ffma2(pk2(a4.x, a4.y), v2, o2[0]);
            o2[1] = ffma2(pk2(a4.z, a4.w), v2, o2[1]);
        }
        float o0, o1, o2f, o3;
        upk2(o2[0], o0, o1);
        upk2(o2[1], o2f, o3);
        int ob = ((r << 8) + i0) * INDIM + (h << 5) + lane;
        g_ao[ob] = o0;
        g_ao[ob + INDIM] = o1;
        g_ao[ob + 2 * INDIM] = o2f;
        g_ao[ob + 3 * INDIM] = o3;
        __syncwarp();
    }
}

// ---------------------------------------------------------------------------
extern "C" void kernel_launch(void* const* d_in, const int* in_sizes, int n_in,
                              void* d_out, int out_size)
{
    const float* z      = (const float*)d_in[0];
    const int*   smask  = (const int*)  d_in[1];
    const float* ln_g   = (const float*)d_in[2];
    const float* ln_b   = (const float*)d_in[3];
    const float* w_qkv  = (const float*)d_in[4];
    const float* w_pair = (const float*)d_in[5];
    const float* w_gate = (const float*)d_in[6];
    const float* b_gate = (const float*)d_in[7];
    const float* w_out  = (const float*)d_in[8];
    const float* b_out  = (const float*)d_in[9];
    float* out = (float*)d_out;

    cudaFuncSetAttribute(proj_mma<0>,
                         cudaFuncAttributeMaxDynamicSharedMemorySize, PROJ_SMEM);
    cudaFuncSetAttribute(proj_mma<1>,
                         cudaFuncAttributeMaxDynamicSharedMemorySize, PROJ_SMEM);
    const int ATT_SMEM = 101376;
    cudaFuncSetAttribute(attn_kernel,
                         cudaFuncAttributeMaxDynamicSharedMemorySize, ATT_SMEM);

    ln_kernel<<<8192, 256>>>(z, ln_g, ln_b);
    prep_w<<<320, 256>>>(w_qkv, w_gate, w_out);
    proj_mma<0><<<512, 256, PROJ_SMEM>>>(b_gate, nullptr, nullptr);
    pb_kernel<<<16384, 128>>>(w_pair);
    attn_kernel<<<dim3(4, 256), 256, ATT_SMEM>>>(smask);
    proj_mma<1><<<512, 256, PROJ_SMEM>>>(nullptr, b_out, out);
}

// round 9
// speedup vs baseline: 1.7019x; 1.2208x over previous
#include <cuda_runtime.h>
#include <cuda_bf16.h>
#include <math.h>
#include <stdint.h>

// ---------------------------------------------------------------------------
// TriangleAttention  (B=1, N=256, IN_DIM=128, H=4, D=32)
// R9: attention ported to warp-level mma.sync (split-bf16 3-pass for S and AV,
//     softmax on register fragments, P->A fragment reuse, ldmatrix.trans V).
// Projections: R8 proj_mma (proven, rel_err 8.7e-6).
// ---------------------------------------------------------------------------

#define NPOS 65536
#define NSEQ 256
#define INDIM 128
#define NH 4
#define HD 32

typedef unsigned long long u64;

// ---------------- scratch ----------------
__device__ __align__(16) float g_zn[NPOS * INDIM];
__device__ __align__(16) float g_q[NPOS * INDIM];      // [r][h][i][d]
__device__ __align__(16) float g_k[NPOS * INDIM];      // [r][h][j][d]
__device__ __align__(16) float g_v[NPOS * INDIM];      // [r][h][j][d]
__device__ __align__(16) float g_pb[NH * NPOS];        // [h][i][j]
__device__ __align__(16) float g_gate[NPOS * INDIM];
__device__ __align__(16) float g_ao[NPOS * INDIM];
__device__ __align__(16) __nv_bfloat16 g_w1h[512 * 128];
__device__ __align__(16) __nv_bfloat16 g_w1l[512 * 128];
__device__ __align__(16) __nv_bfloat16 g_w2h[128 * 128];
__device__ __align__(16) __nv_bfloat16 g_w2l[128 * 128];

// ---------------- helpers ----------------
__device__ __forceinline__ float warp_sum(float v) {
    #pragma unroll
    for (int o = 16; o; o >>= 1) v += __shfl_xor_sync(0xffffffffu, v, o);
    return v;
}
__device__ __forceinline__ uint32_t smem_u32(const void* p) {
    uint32_t a;
    asm("{ .reg .u64 t; cvta.to.shared.u64 t, %1; cvt.u32.u64 %0, t; }"
        : "=r"(a) : "l"(p));
    return a;
}
__device__ __forceinline__ void cvt_split4(float4 a, uint2& hh, uint2& ll) {
    __nv_bfloat16 h0 = __float2bfloat16(a.x), h1 = __float2bfloat16(a.y);
    __nv_bfloat16 h2 = __float2bfloat16(a.z), h3 = __float2bfloat16(a.w);
    __nv_bfloat16 l0 = __float2bfloat16(a.x - __bfloat162float(h0));
    __nv_bfloat16 l1 = __float2bfloat16(a.y - __bfloat162float(h1));
    __nv_bfloat16 l2 = __float2bfloat16(a.z - __bfloat162float(h2));
    __nv_bfloat16 l3 = __float2bfloat16(a.w - __bfloat162float(h3));
    hh.x = ((uint32_t)__bfloat16_as_ushort(h1) << 16) | __bfloat16_as_ushort(h0);
    hh.y = ((uint32_t)__bfloat16_as_ushort(h3) << 16) | __bfloat16_as_ushort(h2);
    ll.x = ((uint32_t)__bfloat16_as_ushort(l1) << 16) | __bfloat16_as_ushort(l0);
    ll.y = ((uint32_t)__bfloat16_as_ushort(l3) << 16) | __bfloat16_as_ushort(l2);
}
__device__ __forceinline__ void pack_split(float f0, float f1,
                                           uint32_t& hi, uint32_t& lo) {
    __nv_bfloat16 h0 = __float2bfloat16(f0), h1 = __float2bfloat16(f1);
    __nv_bfloat16 l0 = __float2bfloat16(f0 - __bfloat162float(h0));
    __nv_bfloat16 l1 = __float2bfloat16(f1 - __bfloat162float(h1));
    hi = ((uint32_t)__bfloat16_as_ushort(h1) << 16) | __bfloat16_as_ushort(h0);
    lo = ((uint32_t)__bfloat16_as_ushort(l1) << 16) | __bfloat16_as_ushort(l0);
}

// ---- warp-level MMA primitives ----
__device__ __forceinline__ void ldsm_x4(uint32_t* r, uint32_t addr) {
    asm volatile("ldmatrix.sync.aligned.m8n8.x4.shared.b16 {%0,%1,%2,%3}, [%4];"
                 : "=r"(r[0]), "=r"(r[1]), "=r"(r[2]), "=r"(r[3]) : "r"(addr));
}
__device__ __forceinline__ void ldsm_x4_t(uint32_t* r, uint32_t addr) {
    asm volatile("ldmatrix.sync.aligned.m8n8.x4.trans.shared.b16 {%0,%1,%2,%3}, [%4];"
                 : "=r"(r[0]), "=r"(r[1]), "=r"(r[2]), "=r"(r[3]) : "r"(addr));
}
__device__ __forceinline__ void ldsm_x2(uint32_t* r, uint32_t addr) {
    asm volatile("ldmatrix.sync.aligned.m8n8.x2.shared.b16 {%0,%1}, [%2];"
                 : "=r"(r[0]), "=r"(r[1]) : "r"(addr));
}
__device__ __forceinline__ void mma_bf16(float* d, const uint32_t* a,
                                         const uint32_t* b) {
    asm volatile(
        "mma.sync.aligned.m16n8k16.row.col.f32.bf16.bf16.f32 "
        "{%0,%1,%2,%3}, {%4,%5,%6,%7}, {%8,%9}, {%0,%1,%2,%3};"
        : "+f"(d[0]), "+f"(d[1]), "+f"(d[2]), "+f"(d[3])
        : "r"(a[0]), "r"(a[1]), "r"(a[2]), "r"(a[3]), "r"(b[0]), "r"(b[1]));
}

// ---------------------------------------------------------------------------
// LayerNorm
// ---------------------------------------------------------------------------
__global__ void __launch_bounds__(256) ln_kernel(
    const float* __restrict__ z, const float* __restrict__ g,
    const float* __restrict__ b)
{
    int w = threadIdx.x >> 5, lane = threadIdx.x & 31;
    int row = blockIdx.x * 8 + w;
    float4 zv = *(const float4*)&z[row * INDIM + (lane << 2)];
    float s  = zv.x + zv.y + zv.z + zv.w;
    float s2 = zv.x * zv.x + zv.y * zv.y + zv.z * zv.z + zv.w * zv.w;
    s = warp_sum(s);
    s2 = warp_sum(s2);
    float mu = s * (1.0f / 128.0f);
    float var = s2 * (1.0f / 128.0f) - mu * mu;
    float rs = rsqrtf(var + 1e-5f);
    float4 gv = *(const float4*)&g[lane << 2];
    float4 bv = *(const float4*)&b[lane << 2];
    float4 o;
    o.x = (zv.x - mu) * rs * gv.x + bv.x;
    o.y = (zv.y - mu) * rs * gv.y + bv.y;
    o.z = (zv.z - mu) * rs * gv.z + bv.z;
    o.w = (zv.w - mu) * rs * gv.w + bv.w;
    *(float4*)&g_zn[row * INDIM + (lane << 2)] = o;
}

// ---------------------------------------------------------------------------
// Weight prep
// ---------------------------------------------------------------------------
__global__ void __launch_bounds__(256) prep_w(
    const float* __restrict__ wqkv, const float* __restrict__ wgate,
    const float* __restrict__ wout)
{
    int idx = blockIdx.x * 256 + threadIdx.x;
    int n = idx >> 7, k = idx & 127;
    float x;
    if (n < 384)      x = wqkv[k * 384 + n];
    else if (n < 512) x = wgate[k * 128 + (n - 384)];
    else              x = wout[k * 128 + (n - 512)];
    __nv_bfloat16 h = __float2bfloat16(x);
    __nv_bfloat16 l = __float2bfloat16(x - __bfloat162float(h));
    if (n < 512) { g_w1h[n * 128 + k] = h; g_w1l[n * 128 + k] = l; }
    else { g_w2h[(n - 512) * 128 + k] = h; g_w2l[(n - 512) * 128 + k] = l; }
}

// ---------------------------------------------------------------------------
// Projection GEMM via mma.sync (unchanged from R8)
// ---------------------------------------------------------------------------
#define PITCHU 68
#define OFF_AH 0
#define OFF_AL 34816
#define OFF_BH 69632
#define OFF_BL 87040
#define PROJ_SMEM 104448

template <int WHICH>
__global__ void __launch_bounds__(256) proj_mma(
    const float* __restrict__ bgate, const float* __restrict__ bout,
    float* __restrict__ dout)
{
    extern __shared__ char smem[];
    uint32_t sb = smem_u32(smem);
    uint32_t* smU = (uint32_t*)smem;

    int tid = threadIdx.x, wid = tid >> 5, lane = tid & 31;
    int warp_m = wid >> 2, warp_n = wid & 3;
    int g = lane >> 2, tg = lane & 3;
    int m0 = blockIdx.x << 7;

    #pragma unroll 4
    for (int t = 0; t < 16; t++) {
        int e4 = tid + (t << 8);
        int m = e4 >> 5;
        int k4 = (e4 & 31) << 2;
        int gi = (m0 + m) * INDIM + k4;
        float4 a;
        if (WHICH == 1) {
            float4 x = *(const float4*)&g_ao[gi];
            float4 gt = *(const float4*)&g_gate[gi];
            a.x = x.x * gt.x; a.y = x.y * gt.y;
            a.z = x.z * gt.z; a.w = x.w * gt.w;
        } else {
            a = *(const float4*)&g_zn[gi];
        }
        uint2 hh, ll;
        cvt_split4(a, hh, ll);
        int du = m * PITCHU + (k4 >> 1);
        *(uint2*)&smU[(OFF_AH >> 2) + du] = hh;
        *(uint2*)&smU[(OFF_AL >> 2) + du] = ll;
    }
    __syncthreads();

    const int NT = (WHICH == 0) ? 8 : 2;
    for (int nt = 0; nt < NT; nt++) {
        int nbase = nt << 6;
        const __nv_bfloat16* WH = (WHICH == 0) ? g_w1h : g_w2h;
        const __nv_bfloat16* WL = (WHICH == 0) ? g_w1l : g_w2l;
        #pragma unroll
        for (int t = 0; t < 8; t++) {
            int f = tid + (t << 8);
            int row = f >> 5;
            int cu2 = (f & 31);
            uint2 hh = *(const uint2*)&WH[(nbase + row) * 128 + (cu2 << 2)];
            uint2 ll = *(const uint2*)&WL[(nbase + row) * 128 + (cu2 << 2)];
            int du = row * PITCHU + (cu2 << 1);
            *(uint2*)&smU[(OFF_BH >> 2) + du] = hh;
            *(uint2*)&smU[(OFF_BL >> 2) + du] = ll;
        }
        __syncthreads();

        float d[4][2][4];
        #pragma unroll
        for (int mt = 0; mt < 4; mt++)
            #pragma unroll
            for (int ntl = 0; ntl < 2; ntl++)
                #pragma unroll
                for (int e = 0; e < 4; e++) d[mt][ntl][e] = 0.0f;

        int arow = (warp_m << 6) + (lane & 15);
        uint32_t a_off = (uint32_t)(arow * 272 + ((lane >> 4) << 4));
        int brow = (warp_n << 4) + (lane & 7);
        uint32_t b_off = (uint32_t)(brow * 272 + (((lane >> 3) & 1) << 4));
        uint32_t b2_off = b_off + 8 * 272;

        #pragma unroll 2
        for (int ks = 0; ks < 8; ks++) {
            uint32_t koff = (uint32_t)(ks << 5);
            uint32_t a[4][4], bh[2][2], bl[2][2];
            #pragma unroll
            for (int mt = 0; mt < 4; mt++)
                ldsm_x4(a[mt], sb + OFF_AH + a_off + (uint32_t)(mt * 16 * 272) + koff);
            ldsm_x2(bh[0], sb + OFF_BH + b_off + koff);
            ldsm_x2(bh[1], sb + OFF_BH + b2_off + koff);
            ldsm_x2(bl[0], sb + OFF_BL + b_off + koff);
            ldsm_x2(bl[1], sb + OFF_BL + b2_off + koff);
            #pragma unroll
            for (int mt = 0; mt < 4; mt++) {
                mma_bf16(d[mt][0], a[mt], bh[0]);
                mma_bf16(d[mt][1], a[mt], bh[1]);
            }
            #pragma unroll
            for (int mt = 0; mt < 4; mt++) {
                mma_bf16(d[mt][0], a[mt], bl[0]);
                mma_bf16(d[mt][1], a[mt], bl[1]);
            }
            #pragma unroll
            for (int mt = 0; mt < 4; mt++)
                ldsm_x4(a[mt], sb + OFF_AL + a_off + (uint32_t)(mt * 16 * 272) + koff);
            #pragma unroll
            for (int mt = 0; mt < 4; mt++) {
                mma_bf16(d[mt][0], a[mt], bh[0]);
                mma_bf16(d[mt][1], a[mt], bh[1]);
            }
        }
        __syncthreads();

        #pragma unroll
        for (int mt = 0; mt < 4; mt++) {
            int p0 = m0 + (warp_m << 6) + (mt << 4) + g;
            #pragma unroll
            for (int ntl = 0; ntl < 2; ntl++) {
                int n = nbase + (warp_n << 4) + (ntl << 3) + (tg << 1);
                #pragma unroll
                for (int half = 0; half < 2; half++) {
                    int p = p0 + half * 8;
                    float v0 = d[mt][ntl][half * 2 + 0];
                    float v1 = d[mt][ntl][half * 2 + 1];
                    if (WHICH == 0) {
                        if (n < 384) {
                            int seg = n >> 7, nl = n & 127, h = nl >> 5, dd = nl & 31;
                            int r = p >> 8, i = p & 255;
                            float* dst = (seg == 0) ? g_q : ((seg == 1) ? g_k : g_v);
                            *(float2*)&dst[((r * NH + h) * NSEQ + i) * HD + dd] =
                                make_float2(v0, v1);
                        } else {
                            int gc = n - 384;
                            float2 bb = *(const float2*)&bgate[gc];
                            float2 v;
                            v.x = 1.0f / (1.0f + __expf(-(v0 + bb.x)));
                            v.y = 1.0f / (1.0f + __expf(-(v1 + bb.y)));
                            *(float2*)&g_gate[p * INDIM + gc] = v;
                        }
                    } else {
                        float2 bb = *(const float2*)&bout[n];
                        *(float2*)&dout[p * INDIM + n] =
                            make_float2(v0 + bb.x, v1 + bb.y);
                    }
                }
            }
        }
    }
}

// ---------------------------------------------------------------------------
// Pair bias
// ---------------------------------------------------------------------------
__global__ void __launch_bounds__(128) pb_kernel(const float* __restrict__ w_pair)
{
    int w = threadIdx.x >> 5, lane = threadIdx.x & 31;
    int p = blockIdx.x * 4 + w;
    float4 zv = *(const float4*)&g_zn[p * INDIM + (lane << 2)];
    const float4* W = (const float4*)w_pair;
    int k0 = lane << 2;
    float4 w0 = W[k0], w1 = W[k0 + 1], w2 = W[k0 + 2], w3 = W[k0 + 3];
    float4 a;
    a.x = zv.x * w0.x + zv.y * w1.x + zv.z * w2.x + zv.w * w3.x;
    a.y = zv.x * w0.y + zv.y * w1.y + zv.z * w2.y + zv.w * w3.y;
    a.z = zv.x * w0.z + zv.y * w1.z + zv.z * w2.z + zv.w * w3.z;
    a.w = zv.x * w0.w + zv.y * w1.w + zv.z * w2.w + zv.w * w3.w;
    a.x = warp_sum(a.x); a.y = warp_sum(a.y);
    a.z = warp_sum(a.z); a.w = warp_sum(a.w);
    if (lane == 0) {
        g_pb[0 * NPOS + p] = a.x;
        g_pb[1 * NPOS + p] = a.y;
        g_pb[2 * NPOS + p] = a.z;
        g_pb[3 * NPOS + p] = a.w;
    }
}

// ---------------------------------------------------------------------------
// Attention via mma.sync. One block per (h, r), 8 warps.
// Q/K/V staged as split bf16, pitch 80B (row step = 20 banks: conflict-free).
// Warp w, pass gp: rows i0 = gp*128 + w*16.
// S frags c[32][4] (j n-tiles), softmax in regs (quad shfl), P->A reuse,
// V via ldmatrix.x4.trans, 1/sum folded into epilogue.
// ---------------------------------------------------------------------------
#define APITCH 80
#define OQH 0
#define OQL 20480
#define OKH 40960
#define OKL 61440
#define OVH 81920
#define OVL 102400
#define OMSK 122880
#define ATT_SMEM 123904

__global__ void __launch_bounds__(256, 1) attn_mma(const int* __restrict__ smask)
{
    extern __shared__ char smc[];
    uint32_t sb = smem_u32(smc);
    int* msk = (int*)(smc + OMSK);

    int h = blockIdx.x, r = blockIdx.y;
    int tid = threadIdx.x, w = tid >> 5, lane = tid & 31;
    int tg = lane & 3, ro = lane >> 2;
    int base = (r * NH + h) << 13;

    // ---- stage Q, K, V (split bf16, pitch 80B) ----
    #pragma unroll
    for (int t = 0; t < 8; t++) {
        int f4 = tid + (t << 8);            // 0..2047
        int row = f4 >> 3;
        int d4 = (f4 & 7) << 2;
        uint32_t doff = (uint32_t)(row * APITCH + (d4 << 1));
        uint2 hh, ll;
        cvt_split4(*(const float4*)&g_q[base + (row << 5) + d4], hh, ll);
        *(uint2*)(smc + OQH + doff) = hh;
        *(uint2*)(smc + OQL + doff) = ll;
        cvt_split4(*(const float4*)&g_k[base + (row << 5) + d4], hh, ll);
        *(uint2*)(smc + OKH + doff) = hh;
        *(uint2*)(smc + OKL + doff) = ll;
        cvt_split4(*(const float4*)&g_v[base + (row << 5) + d4], hh, ll);
        *(uint2*)(smc + OVH + doff) = hh;
        *(uint2*)(smc + OVL + doff) = ll;
    }
    msk[tid] = (smask[tid] == 0) ? 1 : 0;
    __syncthreads();

    const float invs = 0.17677669529663687f;   // 1/sqrt(32)
    int hbase = h << 16;

    for (int gp = 0; gp < 2; gp++) {
        int i0 = (gp << 7) + (w << 4);

        // Q a-frags (2 k-steps x hi/lo)
        uint32_t qh[2][4], ql[2][4];
        uint32_t a_off = (uint32_t)((i0 + (lane & 15)) * APITCH + ((lane >> 4) << 4));
        #pragma unroll
        for (int ks = 0; ks < 2; ks++) {
            ldsm_x4(qh[ks], sb + OQH + a_off + (ks << 5));
            ldsm_x4(ql[ks], sb + OQL + a_off + (ks << 5));
        }

        float c[32][4];
        #pragma unroll
        for (int nt = 0; nt < 32; nt++)
            #pragma unroll
            for (int e = 0; e < 4; e++) c[nt][e] = 0.0f;

        // ---- S = Q K^T (3-pass split bf16) ----
        uint32_t b_off = (uint32_t)(((lane & 7) + ((lane >> 4) << 3)) * APITCH
                                    + (((lane >> 3) & 1) << 4));
        #pragma unroll 4
        for (int nt2 = 0; nt2 < 16; nt2++) {
            #pragma unroll
            for (int ks = 0; ks < 2; ks++) {
                uint32_t kh[4], kl[4];
                uint32_t ad = b_off + (uint32_t)(nt2 * 16 * APITCH) + (ks << 5);
                ldsm_x4(kh, sb + OKH + ad);
                ldsm_x4(kl, sb + OKL + ad);
                mma_bf16(c[2 * nt2],     qh[ks], kh);
                mma_bf16(c[2 * nt2 + 1], qh[ks], kh + 2);
                mma_bf16(c[2 * nt2],     qh[ks], kl);
                mma_bf16(c[2 * nt2 + 1], qh[ks], kl + 2);
                mma_bf16(c[2 * nt2],     ql[ks], kh);
                mma_bf16(c[2 * nt2 + 1], ql[ks], kh + 2);
            }
        }

        // ---- softmax on fragments (rows i_0 = i0+ro, i_1 = +8) ----
        int i_0 = i0 + ro, i_1 = i_0 + 8;
        int mi0 = msk[i_0], mi1 = msk[i_1];
        const float* pb0 = &g_pb[hbase + (i_0 << 8)];
        const float* pb1 = &g_pb[hbase + (i_1 << 8)];
        float mx0 = -1e30f, mx1 = -1e30f;
        #pragma unroll
        for (int nt = 0; nt < 32; nt++) {
            int j0 = (nt << 3) + (tg << 1);
            float2 p0 = *(const float2*)&pb0[j0];
            float2 p1 = *(const float2*)&pb1[j0];
            int2 mj = *(const int2*)&msk[j0];
            float v;
            v = fmaf(c[nt][0], invs, p0.x); if (mi0 ^ mj.x) v = -1e-9f;
            c[nt][0] = v; mx0 = fmaxf(mx0, v);
            v = fmaf(c[nt][1], invs, p0.y); if (mi0 ^ mj.y) v = -1e-9f;
            c[nt][1] = v; mx0 = fmaxf(mx0, v);
            v = fmaf(c[nt][2], invs, p1.x); if (mi1 ^ mj.x) v = -1e-9f;
            c[nt][2] = v; mx1 = fmaxf(mx1, v);
            v = fmaf(c[nt][3], invs, p1.y); if (mi1 ^ mj.y) v = -1e-9f;
            c[nt][3] = v; mx1 = fmaxf(mx1, v);
        }
        mx0 = fmaxf(mx0, __shfl_xor_sync(0xffffffffu, mx0, 1));
        mx0 = fmaxf(mx0, __shfl_xor_sync(0xffffffffu, mx0, 2));
        mx1 = fmaxf(mx1, __shfl_xor_sync(0xffffffffu, mx1, 1));
        mx1 = fmaxf(mx1, __shfl_xor_sync(0xffffffffu, mx1, 2));
        float s0 = 0.0f, s1 = 0.0f;
        #pragma unroll
        for (int nt = 0; nt < 32; nt++) {
            float e0 = __expf(c[nt][0] - mx0); c[nt][0] = e0;
            float e1 = __expf(c[nt][1] - mx0); c[nt][1] = e1;
            float e2 = __expf(c[nt][2] - mx1); c[nt][2] = e2;
            float e3 = __expf(c[nt][3] - mx1); c[nt][3] = e3;
            s0 += e0 + e1;
            s1 += e2 + e3;
        }
        s0 += __shfl_xor_sync(0xffffffffu, s0, 1);
        s0 += __shfl_xor_sync(0xffffffffu, s0, 2);
        s1 += __shfl_xor_sync(0xffffffffu, s1, 1);
        s1 += __shfl_xor_sync(0xffffffffu, s1, 2);
        float inv0 = 1.0f / s0, inv1 = 1.0f / s1;

        // ---- O = P V (3-pass; P frags reused as A operands; 1/s at the end)
        float o[4][4];
        #pragma unroll
        for (int dt = 0; dt < 4; dt++)
            #pragma unroll
            for (int e = 0; e < 4; e++) o[dt][e] = 0.0f;

        #pragma unroll
        for (int kt2 = 0; kt2 < 8; kt2++) {
            uint32_t ah[2][4], al[2][4];
            #pragma unroll
            for (int half = 0; half < 2; half++) {
                int t0 = (kt2 << 2) + (half << 1);
                pack_split(c[t0][0],     c[t0][1],     ah[half][0], al[half][0]);
                pack_split(c[t0][2],     c[t0][3],     ah[half][1], al[half][1]);
                pack_split(c[t0 + 1][0], c[t0 + 1][1], ah[half][2], al[half][2]);
                pack_split(c[t0 + 1][2], c[t0 + 1][3], ah[half][3], al[half][3]);
            }
            uint32_t vrow = (uint32_t)(((kt2 << 5) + lane) * APITCH);
            #pragma unroll
            for (int dt = 0; dt < 4; dt++) {
                uint32_t vh[4], vl[4];
                uint32_t ad = vrow + (uint32_t)(dt << 4);
                ldsm_x4_t(vh, sb + OVH + ad);
                ldsm_x4_t(vl, sb + OVL + ad);
                mma_bf16(o[dt], ah[0], vh);
                mma_bf16(o[dt], ah[1], vh + 2);
                mma_bf16(o[dt], al[0], vh);
                mma_bf16(o[dt], al[1], vh + 2);
                mma_bf16(o[dt], ah[0], vl);
                mma_bf16(o[dt], ah[1], vl + 2);
            }
        }

        int ob0 = (((r << 8) + i_0) << 7) + (h << 5);
        int ob1 = (((r << 8) + i_1) << 7) + (h << 5);
        #pragma unroll
        for (int dt = 0; dt < 4; dt++) {
            int dd = (dt << 3) + (tg << 1);
            *(float2*)&g_ao[ob0 + dd] =
                make_float2(o[dt][0] * inv0, o[dt][1] * inv0);
            *(float2*)&g_ao[ob1 + dd] =
                make_float2(o[dt][2] * inv1, o[dt][3] * inv1);
        }
    }
}

// ---------------------------------------------------------------------------
extern "C" void kernel_launch(void* const* d_in, const int* in_sizes, int n_in,
                              void* d_out, int out_size)
{
    const float* z      = (const float*)d_in[0];
    const int*   smask  = (const int*)  d_in[1];
    const float* ln_g   = (const float*)d_in[2];
    const float* ln_b   = (const float*)d_in[3];
    const float* w_qkv  = (const float*)d_in[4];
    const float* w_pair = (const float*)d_in[5];
    const float* w_gate = (const float*)d_in[6];
    const float* b_gate = (const float*)d_in[7];
    const float* w_out  = (const float*)d_in[8];
    const float* b_out  = (const float*)d_in[9];
    float* out = (float*)d_out;

    cudaFuncSetAttribute(proj_mma<0>,
                         cudaFuncAttributeMaxDynamicSharedMemorySize, PROJ_SMEM);
    cudaFuncSetAttribute(proj_mma<1>,
                         cudaFuncAttributeMaxDynamicSharedMemorySize, PROJ_SMEM);
    cudaFuncSetAttribute(attn_mma,
                         cudaFuncAttributeMaxDynamicSharedMemorySize, ATT_SMEM);

    ln_kernel<<<8192, 256>>>(z, ln_g, ln_b);
    prep_w<<<320, 256>>>(w_qkv, w_gate, w_out);
    proj_mma<0><<<512, 256, PROJ_SMEM>>>(b_gate, nullptr, nullptr);
    pb_kernel<<<16384, 128>>>(w_pair);
    attn_mma<<<dim3(4, 256), 256, ATT_SMEM>>>(smask);
    proj_mma<1><<<512, 256, PROJ_SMEM>>>(nullptr, b_out, out);
}

// round 12
// speedup vs baseline: 1.8127x; 1.0651x over previous
#include <cuda_runtime.h>
#include <cuda_bf16.h>
#include <math.h>
#include <stdint.h>

// ---------------------------------------------------------------------------
// TriangleAttention  (B=1, N=256, IN_DIM=128, H=4, D=32)
// R12 (= R11 resubmit, byte-identical): LN and pair-bias fused into
//     proj_mma<0> (ln_kernel, pb_kernel removed, zn scratch eliminated).
// Attention = R9 mma.sync version.
// ---------------------------------------------------------------------------

#define NPOS 65536
#define NSEQ 256
#define INDIM 128
#define NH 4
#define HD 32

typedef unsigned long long u64;

// ---------------- scratch ----------------
__device__ __align__(16) float g_q[NPOS * INDIM];      // [r][h][i][d]
__device__ __align__(16) float g_k[NPOS * INDIM];      // [r][h][j][d]
__device__ __align__(16) float g_v[NPOS * INDIM];      // [r][h][j][d]
__device__ __align__(16) float g_pb[NH * NPOS];        // [h][i][j]
__device__ __align__(16) float g_gate[NPOS * INDIM];
__device__ __align__(16) float g_ao[NPOS * INDIM];
__device__ __align__(16) __nv_bfloat16 g_w1h[512 * 128];
__device__ __align__(16) __nv_bfloat16 g_w1l[512 * 128];
__device__ __align__(16) __nv_bfloat16 g_w2h[128 * 128];
__device__ __align__(16) __nv_bfloat16 g_w2l[128 * 128];

// ---------------- helpers ----------------
__device__ __forceinline__ float warp_sum(float v) {
    #pragma unroll
    for (int o = 16; o; o >>= 1) v += __shfl_xor_sync(0xffffffffu, v, o);
    return v;
}
__device__ __forceinline__ uint32_t smem_u32(const void* p) {
    uint32_t a;
    asm("{ .reg .u64 t; cvta.to.shared.u64 t, %1; cvt.u32.u64 %0, t; }"
        : "=r"(a) : "l"(p));
    return a;
}
__device__ __forceinline__ void cvt_split4(float4 a, uint2& hh, uint2& ll) {
    __nv_bfloat16 h0 = __float2bfloat16(a.x), h1 = __float2bfloat16(a.y);
    __nv_bfloat16 h2 = __float2bfloat16(a.z), h3 = __float2bfloat16(a.w);
    __nv_bfloat16 l0 = __float2bfloat16(a.x - __bfloat162float(h0));
    __nv_bfloat16 l1 = __float2bfloat16(a.y - __bfloat162float(h1));
    __nv_bfloat16 l2 = __float2bfloat16(a.z - __bfloat162float(h2));
    __nv_bfloat16 l3 = __float2bfloat16(a.w - __bfloat162float(h3));
    hh.x = ((uint32_t)__bfloat16_as_ushort(h1) << 16) | __bfloat16_as_ushort(h0);
    hh.y = ((uint32_t)__bfloat16_as_ushort(h3) << 16) | __bfloat16_as_ushort(h2);
    ll.x = ((uint32_t)__bfloat16_as_ushort(l1) << 16) | __bfloat16_as_ushort(l0);
    ll.y = ((uint32_t)__bfloat16_as_ushort(l3) << 16) | __bfloat16_as_ushort(l2);
}
__device__ __forceinline__ void pack_split(float f0, float f1,
                                           uint32_t& hi, uint32_t& lo) {
    __nv_bfloat16 h0 = __float2bfloat16(f0), h1 = __float2bfloat16(f1);
    __nv_bfloat16 l0 = __float2bfloat16(f0 - __bfloat162float(h0));
    __nv_bfloat16 l1 = __float2bfloat16(f1 - __bfloat162float(h1));
    hi = ((uint32_t)__bfloat16_as_ushort(h1) << 16) | __bfloat16_as_ushort(h0);
    lo = ((uint32_t)__bfloat16_as_ushort(l1) << 16) | __bfloat16_as_ushort(l0);
}

// ---- warp-level MMA primitives ----
__device__ __forceinline__ void ldsm_x4(uint32_t* r, uint32_t addr) {
    asm volatile("ldmatrix.sync.aligned.m8n8.x4.shared.b16 {%0,%1,%2,%3}, [%4];"
                 : "=r"(r[0]), "=r"(r[1]), "=r"(r[2]), "=r"(r[3]) : "r"(addr));
}
__device__ __forceinline__ void ldsm_x4_t(uint32_t* r, uint32_t addr) {
    asm volatile("ldmatrix.sync.aligned.m8n8.x4.trans.shared.b16 {%0,%1,%2,%3}, [%4];"
                 : "=r"(r[0]), "=r"(r[1]), "=r"(r[2]), "=r"(r[3]) : "r"(addr));
}
__device__ __forceinline__ void ldsm_x2(uint32_t* r, uint32_t addr) {
    asm volatile("ldmatrix.sync.aligned.m8n8.x2.shared.b16 {%0,%1}, [%2];"
                 : "=r"(r[0]), "=r"(r[1]) : "r"(addr));
}
__device__ __forceinline__ void mma_bf16(float* d, const uint32_t* a,
                                         const uint32_t* b) {
    asm volatile(
        "mma.sync.aligned.m16n8k16.row.col.f32.bf16.bf16.f32 "
        "{%0,%1,%2,%3}, {%4,%5,%6,%7}, {%8,%9}, {%0,%1,%2,%3};"
        : "+f"(d[0]), "+f"(d[1]), "+f"(d[2]), "+f"(d[3])
        : "r"(a[0]), "r"(a[1]), "r"(a[2]), "r"(a[3]), "r"(b[0]), "r"(b[1]));
}

// ---------------------------------------------------------------------------
// Weight prep
// ---------------------------------------------------------------------------
__global__ void __launch_bounds__(256) prep_w(
    const float* __restrict__ wqkv, const float* __restrict__ wgate,
    const float* __restrict__ wout)
{
    int idx = blockIdx.x * 256 + threadIdx.x;
    int n = idx >> 7, k = idx & 127;
    float x;
    if (n < 384)      x = wqkv[k * 384 + n];
    else if (n < 512) x = wgate[k * 128 + (n - 384)];
    else              x = wout[k * 128 + (n - 512)];
    __nv_bfloat16 h = __float2bfloat16(x);
    __nv_bfloat16 l = __float2bfloat16(x - __bfloat162float(h));
    if (n < 512) { g_w1h[n * 128 + k] = h; g_w1l[n * 128 + k] = l; }
    else { g_w2h[(n - 512) * 128 + k] = h; g_w2l[(n - 512) * 128 + k] = l; }
}

// ---------------------------------------------------------------------------
// Projection GEMM via mma.sync, split-bf16 3-pass.
// WHICH=0: A = LayerNorm(z) computed inline; also computes pair-bias
//          pb = A @ w_pair on warp_n==0 warps. NT=8 (qkv scatter + gate).
// WHICH=1: A = gate*ao, NT=2 (out proj + bias -> dout)
// ---------------------------------------------------------------------------
#define PITCHU 68            // uints per row (272 B pitch)
#define OFF_AH 0
#define OFF_AL 34816
#define OFF_BH 69632
#define OFF_BL 87040
#define OFF_PBH 104448       // 8 rows x 272 B (rows 4-7 zero)
#define OFF_PBL 106624
#define PROJ_SMEM 108800

template <int WHICH>
__global__ void __launch_bounds__(256) proj_mma(
    const float* __restrict__ zin, const float* __restrict__ lng,
    const float* __restrict__ lnb, const float* __restrict__ wpair,
    const float* __restrict__ bgate, const float* __restrict__ bout,
    float* __restrict__ dout)
{
    extern __shared__ char smem[];
    uint32_t sb = smem_u32(smem);
    uint32_t* smU = (uint32_t*)smem;

    int tid = threadIdx.x, wid = tid >> 5, lane = tid & 31;
    int warp_m = wid >> 2, warp_n = wid & 3;
    int g = lane >> 2, tg = lane & 3;
    int m0 = blockIdx.x << 7;

    // hoisted a-frag base (used by pb mma and main loop)
    uint32_t a_off = (uint32_t)(((warp_m << 6) + (lane & 15)) * 272
                                + ((lane >> 4) << 4));

    // ---- A tile staging ----
    if (WHICH == 0) {
        // LayerNorm fused: warp wid handles row t*8+wid, lane = one float4.
        float4 gv = *(const float4*)&lng[lane << 2];
        float4 bv = *(const float4*)&lnb[lane << 2];
        #pragma unroll 2
        for (int t = 0; t < 16; t++) {
            int m = (t << 3) + wid;
            float4 a = *(const float4*)&zin[(m0 + m) * INDIM + (lane << 2)];
            float s  = a.x + a.y + a.z + a.w;
            float s2 = a.x * a.x + a.y * a.y + a.z * a.z + a.w * a.w;
            s = warp_sum(s);
            s2 = warp_sum(s2);
            float mu = s * (1.0f / 128.0f);
            float rs = rsqrtf(s2 * (1.0f / 128.0f) - mu * mu + 1e-5f);
            a.x = (a.x - mu) * rs * gv.x + bv.x;
            a.y = (a.y - mu) * rs * gv.y + bv.y;
            a.z = (a.z - mu) * rs * gv.z + bv.z;
            a.w = (a.w - mu) * rs * gv.w + bv.w;
            uint2 hh, ll;
            cvt_split4(a, hh, ll);
            int du = m * PITCHU + (lane << 1);
            *(uint2*)&smU[(OFF_AH >> 2) + du] = hh;
            *(uint2*)&smU[(OFF_AL >> 2) + du] = ll;
        }
        // stage w_pair as 8-row B tile (rows 0-3 real, 4-7 zero)
        for (int i = tid; i < 272; i += 256) {   // zero rows 4-7 (1088 B = 272 u32)
            smU[((OFF_PBH + 4 * 272) >> 2) + i] = 0;
            smU[((OFF_PBL + 4 * 272) >> 2) + i] = 0;
        }
        if (tid < 128) {
            float4 wp = *(const float4*)&wpair[tid << 2];   // w_pair[k][0..3]
            float v[4] = {wp.x, wp.y, wp.z, wp.w};
            #pragma unroll
            for (int hh2 = 0; hh2 < 4; hh2++) {
                __nv_bfloat16 hb = __float2bfloat16(v[hh2]);
                __nv_bfloat16 lb = __float2bfloat16(v[hh2] - __bfloat162float(hb));
                *(__nv_bfloat16*)(smem + OFF_PBH + hh2 * 272 + (tid << 1)) = hb;
                *(__nv_bfloat16*)(smem + OFF_PBL + hh2 * 272 + (tid << 1)) = lb;
            }
        }
    } else {
        #pragma unroll 4
        for (int t = 0; t < 16; t++) {
            int e4 = tid + (t << 8);
            int m = e4 >> 5;
            int k4 = (e4 & 31) << 2;
            int gi = (m0 + m) * INDIM + k4;
            float4 x = *(const float4*)&g_ao[gi];
            float4 gt = *(const float4*)&g_gate[gi];
            float4 a;
            a.x = x.x * gt.x; a.y = x.y * gt.y;
            a.z = x.z * gt.z; a.w = x.w * gt.w;
            uint2 hh, ll;
            cvt_split4(a, hh, ll);
            int du = m * PITCHU + (k4 >> 1);
            *(uint2*)&smU[(OFF_AH >> 2) + du] = hh;
            *(uint2*)&smU[(OFF_AL >> 2) + du] = ll;
        }
    }
    __syncthreads();

    // ---- pair-bias mini-GEMM (warp_n==0 warps only) ----
    if (WHICH == 0 && warp_n == 0) {
        float dpb[4][4];
        #pragma unroll
        for (int mt = 0; mt < 4; mt++)
            #pragma unroll
            for (int e = 0; e < 4; e++) dpb[mt][e] = 0.0f;
        uint32_t pb_boff = (uint32_t)((lane & 7) * 272 + (((lane >> 3) & 1) << 4));
        #pragma unroll
        for (int ks = 0; ks < 8; ks++) {
            uint32_t koff = (uint32_t)(ks << 5);
            uint32_t bh2[2], bl2[2];
            ldsm_x2(bh2, sb + OFF_PBH + pb_boff + koff);
            ldsm_x2(bl2, sb + OFF_PBL + pb_boff + koff);
            #pragma unroll
            for (int mt = 0; mt < 4; mt++) {
                uint32_t ah[4], al[4];
                uint32_t ad = a_off + (uint32_t)(mt * 16 * 272) + koff;
                ldsm_x4(ah, sb + OFF_AH + ad);
                ldsm_x4(al, sb + OFF_AL + ad);
                mma_bf16(dpb[mt], ah, bh2);
                mma_bf16(dpb[mt], ah, bl2);
                mma_bf16(dpb[mt], al, bh2);
            }
        }
        if (tg < 2) {
            #pragma unroll
            for (int mt = 0; mt < 4; mt++)
                #pragma unroll
                for (int half = 0; half < 2; half++) {
                    int p = m0 + (warp_m << 6) + (mt << 4) + g + (half << 3);
                    g_pb[(tg * 2) * NPOS + p]     = dpb[mt][half * 2 + 0];
                    g_pb[(tg * 2 + 1) * NPOS + p] = dpb[mt][half * 2 + 1];
                }
        }
    }

    const int NT = (WHICH == 0) ? 8 : 2;
    for (int nt = 0; nt < NT; nt++) {
        int nbase = nt << 6;
        const __nv_bfloat16* WH = (WHICH == 0) ? g_w1h : g_w2h;
        const __nv_bfloat16* WL = (WHICH == 0) ? g_w1l : g_w2l;
        #pragma unroll
        for (int t = 0; t < 8; t++) {
            int f = tid + (t << 8);
            int row = f >> 5;
            int cu2 = (f & 31);
            uint2 hh = *(const uint2*)&WH[(nbase + row) * 128 + (cu2 << 2)];
            uint2 ll = *(const uint2*)&WL[(nbase + row) * 128 + (cu2 << 2)];
            int du = row * PITCHU + (cu2 << 1);
            *(uint2*)&smU[(OFF_BH >> 2) + du] = hh;
            *(uint2*)&smU[(OFF_BL >> 2) + du] = ll;
        }
        __syncthreads();

        float d[4][2][4];
        #pragma unroll
        for (int mt = 0; mt < 4; mt++)
            #pragma unroll
            for (int ntl = 0; ntl < 2; ntl++)
                #pragma unroll
                for (int e = 0; e < 4; e++) d[mt][ntl][e] = 0.0f;

        int brow = (warp_n << 4) + (lane & 7);
        uint32_t b_off = (uint32_t)(brow * 272 + (((lane >> 3) & 1) << 4));
        uint32_t b2_off = b_off + 8 * 272;

        #pragma unroll 2
        for (int ks = 0; ks < 8; ks++) {
            uint32_t koff = (uint32_t)(ks << 5);
            uint32_t a[4][4], bh[2][2], bl[2][2];
            #pragma unroll
            for (int mt = 0; mt < 4; mt++)
                ldsm_x4(a[mt], sb + OFF_AH + a_off + (uint32_t)(mt * 16 * 272) + koff);
            ldsm_x2(bh[0], sb + OFF_BH + b_off + koff);
            ldsm_x2(bh[1], sb + OFF_BH + b2_off + koff);
            ldsm_x2(bl[0], sb + OFF_BL + b_off + koff);
            ldsm_x2(bl[1], sb + OFF_BL + b2_off + koff);
            #pragma unroll
            for (int mt = 0; mt < 4; mt++) {
                mma_bf16(d[mt][0], a[mt], bh[0]);
                mma_bf16(d[mt][1], a[mt], bh[1]);
            }
            #pragma unroll
            for (int mt = 0; mt < 4; mt++) {
                mma_bf16(d[mt][0], a[mt], bl[0]);
                mma_bf16(d[mt][1], a[mt], bl[1]);
            }
            #pragma unroll
            for (int mt = 0; mt < 4; mt++)
                ldsm_x4(a[mt], sb + OFF_AL + a_off + (uint32_t)(mt * 16 * 272) + koff);
            #pragma unroll
            for (int mt = 0; mt < 4; mt++) {
                mma_bf16(d[mt][0], a[mt], bh[0]);
                mma_bf16(d[mt][1], a[mt], bh[1]);
            }
        }
        __syncthreads();

        #pragma unroll
        for (int mt = 0; mt < 4; mt++) {
            int p0 = m0 + (warp_m << 6) + (mt << 4) + g;
            #pragma unroll
            for (int ntl = 0; ntl < 2; ntl++) {
                int n = nbase + (warp_n << 4) + (ntl << 3) + (tg << 1);
                #pragma unroll
                for (int half = 0; half < 2; half++) {
                    int p = p0 + (half << 3);
                    float v0 = d[mt][ntl][half * 2 + 0];
                    float v1 = d[mt][ntl][half * 2 + 1];
                    if (WHICH == 0) {
                        if (n < 384) {
                            int seg = n >> 7, nl = n & 127, h = nl >> 5, dd = nl & 31;
                            int r = p >> 8, i = p & 255;
                            float* dst = (seg == 0) ? g_q : ((seg == 1) ? g_k : g_v);
                            *(float2*)&dst[((r * NH + h) * NSEQ + i) * HD + dd] =
                                make_float2(v0, v1);
                        } else {
                            int gc = n - 384;
                            float2 bb = *(const float2*)&bgate[gc];
                            float2 v;
                            v.x = 1.0f / (1.0f + __expf(-(v0 + bb.x)));
                            v.y = 1.0f / (1.0f + __expf(-(v1 + bb.y)));
                            *(float2*)&g_gate[p * INDIM + gc] = v;
                        }
                    } else {
                        float2 bb = *(const float2*)&bout[n];
                        *(float2*)&dout[p * INDIM + n] =
                            make_float2(v0 + bb.x, v1 + bb.y);
                    }
                }
            }
        }
    }
}

// ---------------------------------------------------------------------------
// Attention via mma.sync (unchanged from R9)
// ---------------------------------------------------------------------------
#define APITCH 80
#define OQH 0
#define OQL 20480
#define OKH 40960
#define OKL 61440
#define OVH 81920
#define OVL 102400
#define OMSK 122880
#define ATT_SMEM 123904

__global__ void __launch_bounds__(256, 1) attn_mma(const int* __restrict__ smask)
{
    extern __shared__ char smc[];
    uint32_t sb = smem_u32(smc);
    int* msk = (int*)(smc + OMSK);

    int h = blockIdx.x, r = blockIdx.y;
    int tid = threadIdx.x, w = tid >> 5, lane = tid & 31;
    int tg = lane & 3, ro = lane >> 2;
    int base = (r * NH + h) << 13;

    #pragma unroll
    for (int t = 0; t < 8; t++) {
        int f4 = tid + (t << 8);
        int row = f4 >> 3;
        int d4 = (f4 & 7) << 2;
        uint32_t doff = (uint32_t)(row * APITCH + (d4 << 1));
        uint2 hh, ll;
        cvt_split4(*(const float4*)&g_q[base + (row << 5) + d4], hh, ll);
        *(uint2*)(smc + OQH + doff) = hh;
        *(uint2*)(smc + OQL + doff) = ll;
        cvt_split4(*(const float4*)&g_k[base + (row << 5) + d4], hh, ll);
        *(uint2*)(smc + OKH + doff) = hh;
        *(uint2*)(smc + OKL + doff) = ll;
        cvt_split4(*(const float4*)&g_v[base + (row << 5) + d4], hh, ll);
        *(uint2*)(smc + OVH + doff) = hh;
        *(uint2*)(smc + OVL + doff) = ll;
    }
    msk[tid] = (smask[tid] == 0) ? 1 : 0;
    __syncthreads();

    const float invs = 0.17677669529663687f;
    int hbase = h << 16;

    for (int gp = 0; gp < 2; gp++) {
        int i0 = (gp << 7) + (w << 4);

        uint32_t qh[2][4], ql[2][4];
        uint32_t a_off = (uint32_t)((i0 + (lane & 15)) * APITCH + ((lane >> 4) << 4));
        #pragma unroll
        for (int ks = 0; ks < 2; ks++) {
            ldsm_x4(qh[ks], sb + OQH + a_off + (ks << 5));
            ldsm_x4(ql[ks], sb + OQL + a_off + (ks << 5));
        }

        float c[32][4];
        #pragma unroll
        for (int nt = 0; nt < 32; nt++)
            #pragma unroll
            for (int e = 0; e < 4; e++) c[nt][e] = 0.0f;

        uint32_t b_off = (uint32_t)(((lane & 7) + ((lane >> 4) << 3)) * APITCH
                                    + (((lane >> 3) & 1) << 4));
        #pragma unroll 4
        for (int nt2 = 0; nt2 < 16; nt2++) {
            #pragma unroll
            for (int ks = 0; ks < 2; ks++) {
                uint32_t kh[4], kl[4];
                uint32_t ad = b_off + (uint32_t)(nt2 * 16 * APITCH) + (ks << 5);
                ldsm_x4(kh, sb + OKH + ad);
                ldsm_x4(kl, sb + OKL + ad);
                mma_bf16(c[2 * nt2],     qh[ks], kh);
                mma_bf16(c[2 * nt2 + 1], qh[ks], kh + 2);
                mma_bf16(c[2 * nt2],     qh[ks], kl);
                mma_bf16(c[2 * nt2 + 1], qh[ks], kl + 2);
                mma_bf16(c[2 * nt2],     ql[ks], kh);
                mma_bf16(c[2 * nt2 + 1], ql[ks], kh + 2);
            }
        }

        int i_0 = i0 + ro, i_1 = i_0 + 8;
        int mi0 = msk[i_0], mi1 = msk[i_1];
        const float* pb0 = &g_pb[hbase + (i_0 << 8)];
        const float* pb1 = &g_pb[hbase + (i_1 << 8)];
        float mx0 = -1e30f, mx1 = -1e30f;
        #pragma unroll
        for (int nt = 0; nt < 32; nt++) {
            int j0 = (nt << 3) + (tg << 1);
            float2 p0 = *(const float2*)&pb0[j0];
            float2 p1 = *(const float2*)&pb1[j0];
            int2 mj = *(const int2*)&msk[j0];
            float v;
            v = fmaf(c[nt][0], invs, p0.x); if (mi0 ^ mj.x) v = -1e-9f;
            c[nt][0] = v; mx0 = fmaxf(mx0, v);
            v = fmaf(c[nt][1], invs, p0.y); if (mi0 ^ mj.y) v = -1e-9f;
            c[nt][1] = v; mx0 = fmaxf(mx0, v);
            v = fmaf(c[nt][2], invs, p1.x); if (mi1 ^ mj.x) v = -1e-9f;
            c[nt][2] = v; mx1 = fmaxf(mx1, v);
            v = fmaf(c[nt][3], invs, p1.y); if (mi1 ^ mj.y) v = -1e-9f;
            c[nt][3] = v; mx1 = fmaxf(mx1, v);
        }
        mx0 = fmaxf(mx0, __shfl_xor_sync(0xffffffffu, mx0, 1));
        mx0 = fmaxf(mx0, __shfl_xor_sync(0xffffffffu, mx0, 2));
        mx1 = fmaxf(mx1, __shfl_xor_sync(0xffffffffu, mx1, 1));
        mx1 = fmaxf(mx1, __shfl_xor_sync(0xffffffffu, mx1, 2));
        float s0 = 0.0f, s1 = 0.0f;
        #pragma unroll
        for (int nt = 0; nt < 32; nt++) {
            float e0 = __expf(c[nt][0] - mx0); c[nt][0] = e0;
            float e1 = __expf(c[nt][1] - mx0); c[nt][1] = e1;
            float e2 = __expf(c[nt][2] - mx1); c[nt][2] = e2;
            float e3 = __expf(c[nt][3] - mx1); c[nt][3] = e3;
            s0 += e0 + e1;
            s1 += e2 + e3;
        }
        s0 += __shfl_xor_sync(0xffffffffu, s0, 1);
        s0 += __shfl_xor_sync(0xffffffffu, s0, 2);
        s1 += __shfl_xor_sync(0xffffffffu, s1, 1);
        s1 += __shfl_xor_sync(0xffffffffu, s1, 2);
        float inv0 = 1.0f / s0, inv1 = 1.0f / s1;

        float o[4][4];
        #pragma unroll
        for (int dt = 0; dt < 4; dt++)
            #pragma unroll
            for (int e = 0; e < 4; e++) o[dt][e] = 0.0f;

        #pragma unroll
        for (int kt2 = 0; kt2 < 8; kt2++) {
            uint32_t ah[2][4], al[2][4];
            #pragma unroll
            for (int half = 0; half < 2; half++) {
                int t0 = (kt2 << 2) + (half << 1);
                pack_split(c[t0][0],     c[t0][1],     ah[half][0], al[half][0]);
                pack_split(c[t0][2],     c[t0][3],     ah[half][1], al[half][1]);
                pack_split(c[t0 + 1][0], c[t0 + 1][1], ah[half][2], al[half][2]);
                pack_split(c[t0 + 1][2], c[t0 + 1][3], ah[half][3], al[half][3]);
            }
            uint32_t vrow = (uint32_t)(((kt2 << 5) + lane) * APITCH);
            #pragma unroll
            for (int dt = 0; dt < 4; dt++) {
                uint32_t vh[4], vl[4];
                uint32_t ad = vrow + (uint32_t)(dt << 4);
                ldsm_x4_t(vh, sb + OVH + ad);
                ldsm_x4_t(vl, sb + OVL + ad);
                mma_bf16(o[dt], ah[0], vh);
                mma_bf16(o[dt], ah[1], vh + 2);
                mma_bf16(o[dt], al[0], vh);
                mma_bf16(o[dt], al[1], vh + 2);
                mma_bf16(o[dt], ah[0], vl);
                mma_bf16(o[dt], ah[1], vl + 2);
            }
        }

        int ob0 = (((r << 8) + i_0) << 7) + (h << 5);
        int ob1 = (((r << 8) + i_1) << 7) + (h << 5);
        #pragma unroll
        for (int dt = 0; dt < 4; dt++) {
            int dd = (dt << 3) + (tg << 1);
            *(float2*)&g_ao[ob0 + dd] =
                make_float2(o[dt][0] * inv0, o[dt][1] * inv0);
            *(float2*)&g_ao[ob1 + dd] =
                make_float2(o[dt][2] * inv1, o[dt][3] * inv1);
        }
    }
}

// ---------------------------------------------------------------------------
extern "C" void kernel_launch(void* const* d_in, const int* in_sizes, int n_in,
                              void* d_out, int out_size)
{
    const float* z      = (const float*)d_in[0];
    const int*   smask  = (const int*)  d_in[1];
    const float* ln_g   = (const float*)d_in[2];
    const float* ln_b   = (const float*)d_in[3];
    const float* w_qkv  = (const float*)d_in[4];
    const float* w_pair = (const float*)d_in[5];
    const float* w_gate = (const float*)d_in[6];
    const float* b_gate = (const float*)d_in[7];
    const float* w_out  = (const float*)d_in[8];
    const float* b_out  = (const float*)d_in[9];
    float* out = (float*)d_out;

    cudaFuncSetAttribute(proj_mma<0>,
                         cudaFuncAttributeMaxDynamicSharedMemorySize, PROJ_SMEM);
    cudaFuncSetAttribute(proj_mma<1>,
                         cudaFuncAttributeMaxDynamicSharedMemorySize, PROJ_SMEM);
    cudaFuncSetAttribute(attn_mma,
                         cudaFuncAttributeMaxDynamicSharedMemorySize, ATT_SMEM);

    prep_w<<<320, 256>>>(w_qkv, w_gate, w_out);
    proj_mma<0><<<512, 256, PROJ_SMEM>>>(z, ln_g, ln_b, w_pair,
                                         b_gate, nullptr, nullptr);
    attn_mma<<<dim3(4, 256), 256, ATT_SMEM>>>(smask);
    proj_mma<1><<<512, 256, PROJ_SMEM>>>(nullptr, nullptr, nullptr, nullptr,
                                         nullptr, b_out, out);
}

// round 14
// speedup vs baseline: 1.8565x; 1.0242x over previous
#include <cuda_runtime.h>
#include <cuda_bf16.h>
#include <math.h>
#include <stdint.h>

// ---------------------------------------------------------------------------
// TriangleAttention  (B=1, N=256, IN_DIM=128, H=4, D=32)
// R14 (= R13 resubmit, byte-identical; R11->R12 precedent: broker flake).
//   proj: register double-buffered B tiles (overlap LDG with mma).
//   attn: interleaved accumulators in S (2 nt2-tiles) and AV (2 dt-tiles)
//         to break HMMA dependency chains at 8-warp occupancy.
// Numerics identical to R12 (rel_err ~1.1e-5).
// ---------------------------------------------------------------------------

#define NPOS 65536
#define NSEQ 256
#define INDIM 128
#define NH 4
#define HD 32

typedef unsigned long long u64;

// ---------------- scratch ----------------
__device__ __align__(16) float g_q[NPOS * INDIM];      // [r][h][i][d]
__device__ __align__(16) float g_k[NPOS * INDIM];      // [r][h][j][d]
__device__ __align__(16) float g_v[NPOS * INDIM];      // [r][h][j][d]
__device__ __align__(16) float g_pb[NH * NPOS];        // [h][i][j]
__device__ __align__(16) float g_gate[NPOS * INDIM];
__device__ __align__(16) float g_ao[NPOS * INDIM];
__device__ __align__(16) __nv_bfloat16 g_w1h[512 * 128];
__device__ __align__(16) __nv_bfloat16 g_w1l[512 * 128];
__device__ __align__(16) __nv_bfloat16 g_w2h[128 * 128];
__device__ __align__(16) __nv_bfloat16 g_w2l[128 * 128];

// ---------------- helpers ----------------
__device__ __forceinline__ float warp_sum(float v) {
    #pragma unroll
    for (int o = 16; o; o >>= 1) v += __shfl_xor_sync(0xffffffffu, v, o);
    return v;
}
__device__ __forceinline__ uint32_t smem_u32(const void* p) {
    uint32_t a;
    asm("{ .reg .u64 t; cvta.to.shared.u64 t, %1; cvt.u32.u64 %0, t; }"
        : "=r"(a) : "l"(p));
    return a;
}
__device__ __forceinline__ void cvt_split4(float4 a, uint2& hh, uint2& ll) {
    __nv_bfloat16 h0 = __float2bfloat16(a.x), h1 = __float2bfloat16(a.y);
    __nv_bfloat16 h2 = __float2bfloat16(a.z), h3 = __float2bfloat16(a.w);
    __nv_bfloat16 l0 = __float2bfloat16(a.x - __bfloat162float(h0));
    __nv_bfloat16 l1 = __float2bfloat16(a.y - __bfloat162float(h1));
    __nv_bfloat16 l2 = __float2bfloat16(a.z - __bfloat162float(h2));
    __nv_bfloat16 l3 = __float2bfloat16(a.w - __bfloat162float(h3));
    hh.x = ((uint32_t)__bfloat16_as_ushort(h1) << 16) | __bfloat16_as_ushort(h0);
    hh.y = ((uint32_t)__bfloat16_as_ushort(h3) << 16) | __bfloat16_as_ushort(h2);
    ll.x = ((uint32_t)__bfloat16_as_ushort(l1) << 16) | __bfloat16_as_ushort(l0);
    ll.y = ((uint32_t)__bfloat16_as_ushort(l3) << 16) | __bfloat16_as_ushort(l2);
}
__device__ __forceinline__ void pack_split(float f0, float f1,
                                           uint32_t& hi, uint32_t& lo) {
    __nv_bfloat16 h0 = __float2bfloat16(f0), h1 = __float2bfloat16(f1);
    __nv_bfloat16 l0 = __float2bfloat16(f0 - __bfloat162float(h0));
    __nv_bfloat16 l1 = __float2bfloat16(f1 - __bfloat162float(h1));
    hi = ((uint32_t)__bfloat16_as_ushort(h1) << 16) | __bfloat16_as_ushort(h0);
    lo = ((uint32_t)__bfloat16_as_ushort(l1) << 16) | __bfloat16_as_ushort(l0);
}

// ---- warp-level MMA primitives ----
__device__ __forceinline__ void ldsm_x4(uint32_t* r, uint32_t addr) {
    asm volatile("ldmatrix.sync.aligned.m8n8.x4.shared.b16 {%0,%1,%2,%3}, [%4];"
                 : "=r"(r[0]), "=r"(r[1]), "=r"(r[2]), "=r"(r[3]) : "r"(addr));
}
__device__ __forceinline__ void ldsm_x4_t(uint32_t* r, uint32_t addr) {
    asm volatile("ldmatrix.sync.aligned.m8n8.x4.trans.shared.b16 {%0,%1,%2,%3}, [%4];"
                 : "=r"(r[0]), "=r"(r[1]), "=r"(r[2]), "=r"(r[3]) : "r"(addr));
}
__device__ __forceinline__ void ldsm_x2(uint32_t* r, uint32_t addr) {
    asm volatile("ldmatrix.sync.aligned.m8n8.x2.shared.b16 {%0,%1}, [%2];"
                 : "=r"(r[0]), "=r"(r[1]) : "r"(addr));
}
__device__ __forceinline__ void mma_bf16(float* d, const uint32_t* a,
                                         const uint32_t* b) {
    asm volatile(
        "mma.sync.aligned.m16n8k16.row.col.f32.bf16.bf16.f32 "
        "{%0,%1,%2,%3}, {%4,%5,%6,%7}, {%8,%9}, {%0,%1,%2,%3};"
        : "+f"(d[0]), "+f"(d[1]), "+f"(d[2]), "+f"(d[3])
        : "r"(a[0]), "r"(a[1]), "r"(a[2]), "r"(a[3]), "r"(b[0]), "r"(b[1]));
}

// ---------------------------------------------------------------------------
// Weight prep
// ---------------------------------------------------------------------------
__global__ void __launch_bounds__(256) prep_w(
    const float* __restrict__ wqkv, const float* __restrict__ wgate,
    const float* __restrict__ wout)
{
    int idx = blockIdx.x * 256 + threadIdx.x;
    int n = idx >> 7, k = idx & 127;
    float x;
    if (n < 384)      x = wqkv[k * 384 + n];
    else if (n < 512) x = wgate[k * 128 + (n - 384)];
    else              x = wout[k * 128 + (n - 512)];
    __nv_bfloat16 h = __float2bfloat16(x);
    __nv_bfloat16 l = __float2bfloat16(x - __bfloat162float(h));
    if (n < 512) { g_w1h[n * 128 + k] = h; g_w1l[n * 128 + k] = l; }
    else { g_w2h[(n - 512) * 128 + k] = h; g_w2l[(n - 512) * 128 + k] = l; }
}

// ---------------------------------------------------------------------------
// Projection GEMM via mma.sync, split-bf16 3-pass, double-buffered B.
// WHICH=0: A = LayerNorm(z) inline; pb = A @ w_pair on warp_n==0. NT=8.
// WHICH=1: A = gate*ao, NT=2 (out proj + bias -> dout)
// ---------------------------------------------------------------------------
#define PITCHU 68            // uints per row (272 B pitch)
#define OFF_AH 0
#define OFF_AL 34816
#define OFF_BH 69632
#define OFF_BL 87040
#define OFF_PBH 104448       // 8 rows x 272 B (rows 4-7 zero)
#define OFF_PBL 106624
#define PROJ_SMEM 108800

template <int WHICH>
__global__ void __launch_bounds__(256) proj_mma(
    const float* __restrict__ zin, const float* __restrict__ lng,
    const float* __restrict__ lnb, const float* __restrict__ wpair,
    const float* __restrict__ bgate, const float* __restrict__ bout,
    float* __restrict__ dout)
{
    extern __shared__ char smem[];
    uint32_t sb = smem_u32(smem);
    uint32_t* smU = (uint32_t*)smem;

    int tid = threadIdx.x, wid = tid >> 5, lane = tid & 31;
    int warp_m = wid >> 2, warp_n = wid & 3;
    int g = lane >> 2, tg = lane & 3;
    int m0 = blockIdx.x << 7;

    uint32_t a_off = (uint32_t)(((warp_m << 6) + (lane & 15)) * 272
                                + ((lane >> 4) << 4));

    const __nv_bfloat16* WH = (WHICH == 0) ? g_w1h : g_w2h;
    const __nv_bfloat16* WL = (WHICH == 0) ? g_w1l : g_w2l;

    // ---- A tile staging ----
    if (WHICH == 0) {
        float4 gv = *(const float4*)&lng[lane << 2];
        float4 bv = *(const float4*)&lnb[lane << 2];
        #pragma unroll 2
        for (int t = 0; t < 16; t++) {
            int m = (t << 3) + wid;
            float4 a = *(const float4*)&zin[(m0 + m) * INDIM + (lane << 2)];
            float s  = a.x + a.y + a.z + a.w;
            float s2 = a.x * a.x + a.y * a.y + a.z * a.z + a.w * a.w;
            s = warp_sum(s);
            s2 = warp_sum(s2);
            float mu = s * (1.0f / 128.0f);
            float rs = rsqrtf(s2 * (1.0f / 128.0f) - mu * mu + 1e-5f);
            a.x = (a.x - mu) * rs * gv.x + bv.x;
            a.y = (a.y - mu) * rs * gv.y + bv.y;
            a.z = (a.z - mu) * rs * gv.z + bv.z;
            a.w = (a.w - mu) * rs * gv.w + bv.w;
            uint2 hh, ll;
            cvt_split4(a, hh, ll);
            int du = m * PITCHU + (lane << 1);
            *(uint2*)&smU[(OFF_AH >> 2) + du] = hh;
            *(uint2*)&smU[(OFF_AL >> 2) + du] = ll;
        }
        for (int i = tid; i < 272; i += 256) {
            smU[((OFF_PBH + 4 * 272) >> 2) + i] = 0;
            smU[((OFF_PBL + 4 * 272) >> 2) + i] = 0;
        }
        if (tid < 128) {
            float4 wp = *(const float4*)&wpair[tid << 2];
            float v[4] = {wp.x, wp.y, wp.z, wp.w};
            #pragma unroll
            for (int hh2 = 0; hh2 < 4; hh2++) {
                __nv_bfloat16 hb = __float2bfloat16(v[hh2]);
                __nv_bfloat16 lb = __float2bfloat16(v[hh2] - __bfloat162float(hb));
                *(__nv_bfloat16*)(smem + OFF_PBH + hh2 * 272 + (tid << 1)) = hb;
                *(__nv_bfloat16*)(smem + OFF_PBL + hh2 * 272 + (tid << 1)) = lb;
            }
        }
    } else {
        #pragma unroll 4
        for (int t = 0; t < 16; t++) {
            int e4 = tid + (t << 8);
            int m = e4 >> 5;
            int k4 = (e4 & 31) << 2;
            int gi = (m0 + m) * INDIM + k4;
            float4 x = *(const float4*)&g_ao[gi];
            float4 gt = *(const float4*)&g_gate[gi];
            float4 a;
            a.x = x.x * gt.x; a.y = x.y * gt.y;
            a.z = x.z * gt.z; a.w = x.w * gt.w;
            uint2 hh, ll;
            cvt_split4(a, hh, ll);
            int du = m * PITCHU + (k4 >> 1);
            *(uint2*)&smU[(OFF_AH >> 2) + du] = hh;
            *(uint2*)&smU[(OFF_AL >> 2) + du] = ll;
        }
    }

    // prefetch B tile nt=0 into registers
    uint2 bh_pre[8], bl_pre[8];
    #pragma unroll
    for (int t = 0; t < 8; t++) {
        int f = tid + (t << 8);
        int row = f >> 5;
        int cu2 = f & 31;
        bh_pre[t] = *(const uint2*)&WH[row * 128 + (cu2 << 2)];
        bl_pre[t] = *(const uint2*)&WL[row * 128 + (cu2 << 2)];
    }
    __syncthreads();

    // ---- pair-bias mini-GEMM (warp_n==0 warps only) ----
    if (WHICH == 0 && warp_n == 0) {
        float dpb[4][4];
        #pragma unroll
        for (int mt = 0; mt < 4; mt++)
            #pragma unroll
            for (int e = 0; e < 4; e++) dpb[mt][e] = 0.0f;
        uint32_t pb_boff = (uint32_t)((lane & 7) * 272 + (((lane >> 3) & 1) << 4));
        #pragma unroll
        for (int ks = 0; ks < 8; ks++) {
            uint32_t koff = (uint32_t)(ks << 5);
            uint32_t bh2[2], bl2[2];
            ldsm_x2(bh2, sb + OFF_PBH + pb_boff + koff);
            ldsm_x2(bl2, sb + OFF_PBL + pb_boff + koff);
            #pragma unroll
            for (int mt = 0; mt < 4; mt++) {
                uint32_t ah[4], al[4];
                uint32_t ad = a_off + (uint32_t)(mt * 16 * 272) + koff;
                ldsm_x4(ah, sb + OFF_AH + ad);
                ldsm_x4(al, sb + OFF_AL + ad);
                mma_bf16(dpb[mt], ah, bh2);
                mma_bf16(dpb[mt], ah, bl2);
                mma_bf16(dpb[mt], al, bh2);
            }
        }
        if (tg < 2) {
            #pragma unroll
            for (int mt = 0; mt < 4; mt++)
                #pragma unroll
                for (int half = 0; half < 2; half++) {
                    int p = m0 + (warp_m << 6) + (mt << 4) + g + (half << 3);
                    g_pb[(tg * 2) * NPOS + p]     = dpb[mt][half * 2 + 0];
                    g_pb[(tg * 2 + 1) * NPOS + p] = dpb[mt][half * 2 + 1];
                }
        }
    }

    const int NT = (WHICH == 0) ? 8 : 2;
    for (int nt = 0; nt < NT; nt++) {
        // store prefetched B tile to smem
        #pragma unroll
        for (int t = 0; t < 8; t++) {
            int f = tid + (t << 8);
            int row = f >> 5;
            int cu2 = f & 31;
            int du = row * PITCHU + (cu2 << 1);
            *(uint2*)&smU[(OFF_BH >> 2) + du] = bh_pre[t];
            *(uint2*)&smU[(OFF_BL >> 2) + du] = bl_pre[t];
        }
        __syncthreads();

        // prefetch next B tile (overlaps with mma below)
        if (nt + 1 < NT) {
            int nb2 = (nt + 1) << 6;
            #pragma unroll
            for (int t = 0; t < 8; t++) {
                int f = tid + (t << 8);
                int row = f >> 5;
                int cu2 = f & 31;
                bh_pre[t] = *(const uint2*)&WH[(nb2 + row) * 128 + (cu2 << 2)];
                bl_pre[t] = *(const uint2*)&WL[(nb2 + row) * 128 + (cu2 << 2)];
            }
        }

        int nbase = nt << 6;
        float d[4][2][4];
        #pragma unroll
        for (int mt = 0; mt < 4; mt++)
            #pragma unroll
            for (int ntl = 0; ntl < 2; ntl++)
                #pragma unroll
                for (int e = 0; e < 4; e++) d[mt][ntl][e] = 0.0f;

        int brow = (warp_n << 4) + (lane & 7);
        uint32_t b_off = (uint32_t)(brow * 272 + (((lane >> 3) & 1) << 4));
        uint32_t b2_off = b_off + 8 * 272;

        #pragma unroll 2
        for (int ks = 0; ks < 8; ks++) {
            uint32_t koff = (uint32_t)(ks << 5);
            uint32_t a[4][4], bh[2][2], bl[2][2];
            #pragma unroll
            for (int mt = 0; mt < 4; mt++)
                ldsm_x4(a[mt], sb + OFF_AH + a_off + (uint32_t)(mt * 16 * 272) + koff);
            ldsm_x2(bh[0], sb + OFF_BH + b_off + koff);
            ldsm_x2(bh[1], sb + OFF_BH + b2_off + koff);
            ldsm_x2(bl[0], sb + OFF_BL + b_off + koff);
            ldsm_x2(bl[1], sb + OFF_BL + b2_off + koff);
            #pragma unroll
            for (int mt = 0; mt < 4; mt++) {
                mma_bf16(d[mt][0], a[mt], bh[0]);
                mma_bf16(d[mt][1], a[mt], bh[1]);
            }
            #pragma unroll
            for (int mt = 0; mt < 4; mt++) {
                mma_bf16(d[mt][0], a[mt], bl[0]);
                mma_bf16(d[mt][1], a[mt], bl[1]);
            }
            #pragma unroll
            for (int mt = 0; mt < 4; mt++)
                ldsm_x4(a[mt], sb + OFF_AL + a_off + (uint32_t)(mt * 16 * 272) + koff);
            #pragma unroll
            for (int mt = 0; mt < 4; mt++) {
                mma_bf16(d[mt][0], a[mt], bh[0]);
                mma_bf16(d[mt][1], a[mt], bh[1]);
            }
        }
        __syncthreads();

        #pragma unroll
        for (int mt = 0; mt < 4; mt++) {
            int p0 = m0 + (warp_m << 6) + (mt << 4) + g;
            #pragma unroll
            for (int ntl = 0; ntl < 2; ntl++) {
                int n = nbase + (warp_n << 4) + (ntl << 3) + (tg << 1);
                #pragma unroll
                for (int half = 0; half < 2; half++) {
                    int p = p0 + (half << 3);
                    float v0 = d[mt][ntl][half * 2 + 0];
                    float v1 = d[mt][ntl][half * 2 + 1];
                    if (WHICH == 0) {
                        if (n < 384) {
                            int seg = n >> 7, nl = n & 127, h = nl >> 5, dd = nl & 31;
                            int r = p >> 8, i = p & 255;
                            float* dst = (seg == 0) ? g_q : ((seg == 1) ? g_k : g_v);
                            *(float2*)&dst[((r * NH + h) * NSEQ + i) * HD + dd] =
                                make_float2(v0, v1);
                        } else {
                            int gc = n - 384;
                            float2 bb = *(const float2*)&bgate[gc];
                            float2 v;
                            v.x = 1.0f / (1.0f + __expf(-(v0 + bb.x)));
                            v.y = 1.0f / (1.0f + __expf(-(v1 + bb.y)));
                            *(float2*)&g_gate[p * INDIM + gc] = v;
                        }
                    } else {
                        float2 bb = *(const float2*)&bout[n];
                        *(float2*)&dout[p * INDIM + n] =
                            make_float2(v0 + bb.x, v1 + bb.y);
                    }
                }
            }
        }
    }
}

// ---------------------------------------------------------------------------
// Attention via mma.sync; interleaved accumulators.
// ---------------------------------------------------------------------------
#define APITCH 80
#define OQH 0
#define OQL 20480
#define OKH 40960
#define OKL 61440
#define OVH 81920
#define OVL 102400
#define OMSK 122880
#define ATT_SMEM 123904

__global__ void __launch_bounds__(256, 1) attn_mma(const int* __restrict__ smask)
{
    extern __shared__ char smc[];
    uint32_t sb = smem_u32(smc);
    int* msk = (int*)(smc + OMSK);

    int h = blockIdx.x, r = blockIdx.y;
    int tid = threadIdx.x, w = tid >> 5, lane = tid & 31;
    int tg = lane & 3, ro = lane >> 2;
    int base = (r * NH + h) << 13;

    #pragma unroll
    for (int t = 0; t < 8; t++) {
        int f4 = tid + (t << 8);
        int row = f4 >> 3;
        int d4 = (f4 & 7) << 2;
        uint32_t doff = (uint32_t)(row * APITCH + (d4 << 1));
        uint2 hh, ll;
        cvt_split4(*(const float4*)&g_q[base + (row << 5) + d4], hh, ll);
        *(uint2*)(smc + OQH + doff) = hh;
        *(uint2*)(smc + OQL + doff) = ll;
        cvt_split4(*(const float4*)&g_k[base + (row << 5) + d4], hh, ll);
        *(uint2*)(smc + OKH + doff) = hh;
        *(uint2*)(smc + OKL + doff) = ll;
        cvt_split4(*(const float4*)&g_v[base + (row << 5) + d4], hh, ll);
        *(uint2*)(smc + OVH + doff) = hh;
        *(uint2*)(smc + OVL + doff) = ll;
    }
    msk[tid] = (smask[tid] == 0) ? 1 : 0;
    __syncthreads();

    const float invs = 0.17677669529663687f;
    int hbase = h << 16;

    for (int gp = 0; gp < 2; gp++) {
        int i0 = (gp << 7) + (w << 4);

        uint32_t qh[2][4], ql[2][4];
        uint32_t a_off = (uint32_t)((i0 + (lane & 15)) * APITCH + ((lane >> 4) << 4));
        #pragma unroll
        for (int ks = 0; ks < 2; ks++) {
            ldsm_x4(qh[ks], sb + OQH + a_off + (ks << 5));
            ldsm_x4(ql[ks], sb + OQL + a_off + (ks << 5));
        }

        float c[32][4];
        #pragma unroll
        for (int nt = 0; nt < 32; nt++)
            #pragma unroll
            for (int e = 0; e < 4; e++) c[nt][e] = 0.0f;

        // ---- S = Q K^T : two nt2 tiles interleaved per step ----
        uint32_t b_off = (uint32_t)(((lane & 7) + ((lane >> 4) << 3)) * APITCH
                                    + (((lane >> 3) & 1) << 4));
        #pragma unroll 2
        for (int nt4 = 0; nt4 < 8; nt4++) {
            int na = nt4 << 2;
            #pragma unroll
            for (int ks = 0; ks < 2; ks++) {
                uint32_t khA[4], klA[4], khB[4], klB[4];
                uint32_t adA = b_off + (uint32_t)((nt4 << 1) * 16 * APITCH) + (ks << 5);
                uint32_t adB = adA + (uint32_t)(16 * APITCH);
                ldsm_x4(khA, sb + OKH + adA);
                ldsm_x4(khB, sb + OKH + adB);
                ldsm_x4(klA, sb + OKL + adA);
                ldsm_x4(klB, sb + OKL + adB);
                mma_bf16(c[na],     qh[ks], khA);
                mma_bf16(c[na + 2], qh[ks], khB);
                mma_bf16(c[na + 1], qh[ks], khA + 2);
                mma_bf16(c[na + 3], qh[ks], khB + 2);
                mma_bf16(c[na],     qh[ks], klA);
                mma_bf16(c[na + 2], qh[ks], klB);
                mma_bf16(c[na + 1], qh[ks], klA + 2);
                mma_bf16(c[na + 3], qh[ks], klB + 2);
                mma_bf16(c[na],     ql[ks], khA);
                mma_bf16(c[na + 2], ql[ks], khB);
                mma_bf16(c[na + 1], ql[ks], khA + 2);
                mma_bf16(c[na + 3], ql[ks], khB + 2);
            }
        }

        // ---- softmax on fragments ----
        int i_0 = i0 + ro, i_1 = i_0 + 8;
        int mi0 = msk[i_0], mi1 = msk[i_1];
        const float* pb0 = &g_pb[hbase + (i_0 << 8)];
        const float* pb1 = &g_pb[hbase + (i_1 << 8)];
        float mx0 = -1e30f, mx1 = -1e30f;
        #pragma unroll
        for (int nt = 0; nt < 32; nt++) {
            int j0 = (nt << 3) + (tg << 1);
            float2 p0 = *(const float2*)&pb0[j0];
            float2 p1 = *(const float2*)&pb1[j0];
            int2 mj = *(const int2*)&msk[j0];
            float v;
            v = fmaf(c[nt][0], invs, p0.x); if (mi0 ^ mj.x) v = -1e-9f;
            c[nt][0] = v; mx0 = fmaxf(mx0, v);
            v = fmaf(c[nt][1], invs, p0.y); if (mi0 ^ mj.y) v = -1e-9f;
            c[nt][1] = v; mx0 = fmaxf(mx0, v);
            v = fmaf(c[nt][2], invs, p1.x); if (mi1 ^ mj.x) v = -1e-9f;
            c[nt][2] = v; mx1 = fmaxf(mx1, v);
            v = fmaf(c[nt][3], invs, p1.y); if (mi1 ^ mj.y) v = -1e-9f;
            c[nt][3] = v; mx1 = fmaxf(mx1, v);
        }
        mx0 = fmaxf(mx0, __shfl_xor_sync(0xffffffffu, mx0, 1));
        mx0 = fmaxf(mx0, __shfl_xor_sync(0xffffffffu, mx0, 2));
        mx1 = fmaxf(mx1, __shfl_xor_sync(0xffffffffu, mx1, 1));
        mx1 = fmaxf(mx1, __shfl_xor_sync(0xffffffffu, mx1, 2));
        float s0 = 0.0f, s1 = 0.0f;
        #pragma unroll
        for (int nt = 0; nt < 32; nt++) {
            float e0 = __expf(c[nt][0] - mx0); c[nt][0] = e0;
            float e1 = __expf(c[nt][1] - mx0); c[nt][1] = e1;
            float e2 = __expf(c[nt][2] - mx1); c[nt][2] = e2;
            float e3 = __expf(c[nt][3] - mx1); c[nt][3] = e3;
            s0 += e0 + e1;
            s1 += e2 + e3;
        }
        s0 += __shfl_xor_sync(0xffffffffu, s0, 1);
        s0 += __shfl_xor_sync(0xffffffffu, s0, 2);
        s1 += __shfl_xor_sync(0xffffffffu, s1, 1);
        s1 += __shfl_xor_sync(0xffffffffu, s1, 2);
        float inv0 = 1.0f / s0, inv1 = 1.0f / s1;

        // ---- O = P V : two dt tiles interleaved per step ----
        float o[4][4];
        #pragma unroll
        for (int dt = 0; dt < 4; dt++)
            #pragma unroll
            for (int e = 0; e < 4; e++) o[dt][e] = 0.0f;

        #pragma unroll
        for (int kt2 = 0; kt2 < 8; kt2++) {
            uint32_t ah[2][4], al[2][4];
            #pragma unroll
            for (int half = 0; half < 2; half++) {
                int t0 = (kt2 << 2) + (half << 1);
                pack_split(c[t0][0],     c[t0][1],     ah[half][0], al[half][0]);
                pack_split(c[t0][2],     c[t0][3],     ah[half][1], al[half][1]);
                pack_split(c[t0 + 1][0], c[t0 + 1][1], ah[half][2], al[half][2]);
                pack_split(c[t0 + 1][2], c[t0 + 1][3], ah[half][3], al[half][3]);
            }
            uint32_t vrow = (uint32_t)(((kt2 << 5) + lane) * APITCH);
            #pragma unroll
            for (int dp = 0; dp < 2; dp++) {
                uint32_t vh0[4], vl0[4], vh1[4], vl1[4];
                uint32_t ad0 = vrow + (uint32_t)((dp << 1) << 4);
                uint32_t ad1 = ad0 + 16;
                ldsm_x4_t(vh0, sb + OVH + ad0);
                ldsm_x4_t(vh1, sb + OVH + ad1);
                ldsm_x4_t(vl0, sb + OVL + ad0);
                ldsm_x4_t(vl1, sb + OVL + ad1);
                float* oa = o[dp << 1];
                float* ob = o[(dp << 1) + 1];
                mma_bf16(oa, ah[0], vh0);
                mma_bf16(ob, ah[0], vh1);
                mma_bf16(oa, ah[1], vh0 + 2);
                mma_bf16(ob, ah[1], vh1 + 2);
                mma_bf16(oa, al[0], vh0);
                mma_bf16(ob, al[0], vh1);
                mma_bf16(oa, al[1], vh0 + 2);
                mma_bf16(ob, al[1], vh1 + 2);
                mma_bf16(oa, ah[0], vl0);
                mma_bf16(ob, ah[0], vl1);
                mma_bf16(oa, ah[1], vl0 + 2);
                mma_bf16(ob, ah[1], vl1 + 2);
            }
        }

        int ob0 = (((r << 8) + i_0) << 7) + (h << 5);
        int ob1 = (((r << 8) + i_1) << 7) + (h << 5);
        #pragma unroll
        for (int dt = 0; dt < 4; dt++) {
            int dd = (dt << 3) + (tg << 1);
            *(float2*)&g_ao[ob0 + dd] =
                make_float2(o[dt][0] * inv0, o[dt][1] * inv0);
            *(float2*)&g_ao[ob1 + dd] =
                make_float2(o[dt][2] * inv1, o[dt][3] * inv1);
        }
    }
}

// ---------------------------------------------------------------------------
extern "C" void kernel_launch(void* const* d_in, const int* in_sizes, int n_in,
                              void* d_out, int out_size)
{
    const float* z      = (const float*)d_in[0];
    const int*   smask  = (const int*)  d_in[1];
    const float* ln_g   = (const float*)d_in[2];
    const float* ln_b   = (const float*)d_in[3];
    const float* w_qkv  = (const float*)d_in[4];
    const float* w_pair = (const float*)d_in[5];
    const float* w_gate = (const float*)d_in[6];
    const float* b_gate = (const float*)d_in[7];
    const float* w_out  = (const float*)d_in[8];
    const float* b_out  = (const float*)d_in[9];
    float* out = (float*)d_out;

    cudaFuncSetAttribute(proj_mma<0>,
                         cudaFuncAttributeMaxDynamicSharedMemorySize, PROJ_SMEM);
    cudaFuncSetAttribute(proj_mma<1>,
                         cudaFuncAttributeMaxDynamicSharedMemorySize, PROJ_SMEM);
    cudaFuncSetAttribute(attn_mma,
                         cudaFuncAttributeMaxDynamicSharedMemorySize, ATT_SMEM);

    prep_w<<<320, 256>>>(w_qkv, w_gate, w_out);
    proj_mma<0><<<512, 256, PROJ_SMEM>>>(z, ln_g, ln_b, w_pair,
                                         b_gate, nullptr, nullptr);
    attn_mma<<<dim3(4, 256), 256, ATT_SMEM>>>(smask);
    proj_mma<1><<<512, 256, PROJ_SMEM>>>(nullptr, nullptr, nullptr, nullptr,
                                         nullptr, b_out, out);
}